// round 12
// baseline (speedup 1.0000x reference)
#include <cuda_runtime.h>
#include <cuda_fp16.h>
#include <cstdint>

// Problem constants
#define BB   2
#define SS   1024
#define DD   1024
#define HH   16
#define HDIM 64
#define WIN  256
#define FF   4096
#define MR   (BB*SS)   // 2048 rows

// ---------------- scratch (device globals; no allocation allowed) ----------
__device__ float  g_v   [MR*DD];
__device__ float  g_x1  [MR*DD];
__device__ float  g_gate[MR*FF];
__device__ __half g_hh  [MR*DD];    // rmsnorm1 out (fp16, GEMM A)
__device__ __half g_h2h [MR*DD];    // rmsnorm2 out
__device__ __half g_aoh [MR*DD];    // attn context out
__device__ __half g_acth[MR*FF];    // silu(gate)*up
__device__ __half g_qhi [MR*DD];
__device__ __half g_qlo [MR*DD];
__device__ __half g_khi [MR*DD];
__device__ __half g_klo [MR*DD];
__device__ float  g_tbl [SS*64];    // rope cos/sin table
__device__ __half g_wh  [16*1024*1024];  // fp16 weights: wq wk wv wo gw uw dw

// ---------------- common PTX helpers ---------------------------------------
__device__ __forceinline__ void cp16(void* smem_dst, const void* gsrc) {
    uint32_t s = (uint32_t)__cvta_generic_to_shared(smem_dst);
    asm volatile("cp.async.cg.shared.global [%0], [%1], 16;\n" :: "r"(s), "l"(gsrc));
}
__device__ __forceinline__ uint32_t f2tf32(float x) {
    uint32_t u;
    asm("cvt.rna.tf32.f32 %0, %1;" : "=r"(u) : "f"(x));
    return u;
}
__device__ __forceinline__ float rnd_tf32(float x) {
    return __uint_as_float(f2tf32(x));
}
__device__ __forceinline__ void mma8(float* d, const uint32_t* a, const uint32_t* b) {
    asm volatile(
        "mma.sync.aligned.m16n8k8.row.col.f32.tf32.tf32.f32 "
        "{%0,%1,%2,%3}, {%4,%5,%6,%7}, {%8,%9}, {%0,%1,%2,%3};\n"
        : "+f"(d[0]), "+f"(d[1]), "+f"(d[2]), "+f"(d[3])
        : "r"(a[0]), "r"(a[1]), "r"(a[2]), "r"(a[3]), "r"(b[0]), "r"(b[1]));
}
__device__ __forceinline__ void mma16h(float* d, const uint32_t* a, const uint32_t* b) {
    asm volatile(
        "mma.sync.aligned.m16n8k16.row.col.f32.f16.f16.f32 "
        "{%0,%1,%2,%3}, {%4,%5,%6,%7}, {%8,%9}, {%0,%1,%2,%3};\n"
        : "+f"(d[0]), "+f"(d[1]), "+f"(d[2]), "+f"(d[3])
        : "r"(a[0]), "r"(a[1]), "r"(a[2]), "r"(a[3]), "r"(b[0]), "r"(b[1]));
}
__device__ __forceinline__ void ldmx4(uint32_t* r, uint32_t addr) {
    asm volatile("ldmatrix.sync.aligned.m8n8.x4.shared.b16 {%0,%1,%2,%3}, [%4];"
                 : "=r"(r[0]), "=r"(r[1]), "=r"(r[2]), "=r"(r[3]) : "r"(addr));
}
__device__ __forceinline__ void ldmx2(uint32_t* r, uint32_t addr) {
    asm volatile("ldmatrix.sync.aligned.m8n8.x2.shared.b16 {%0,%1}, [%2];"
                 : "=r"(r[0]), "=r"(r[1]) : "r"(addr));
}
__device__ __forceinline__ uint32_t smem_u32(const void* p) {
    return (uint32_t)__cvta_generic_to_shared(p);
}

// ---------------- elementwise kernels ---------------------------------------
struct WSet {
    const float4* src[7];
    __half* dst[7];
    int n4[7];
};

__global__ void round_weights_kernel(WSet ws) {
    int reg = blockIdx.y;
    int i = blockIdx.x * 256 + threadIdx.x;
    if (i < ws.n4[reg]) {
        float4 v = ws.src[reg][i];
        __half2 h01 = __floats2half2_rn(v.x, v.y);
        __half2 h23 = __floats2half2_rn(v.z, v.w);
        uint2 o;
        o.x = *(uint32_t*)&h01;
        o.y = *(uint32_t*)&h23;
        ((uint2*)ws.dst[reg])[i] = o;
    }
}

// rope table: tbl[s*64 + i] = cos(s * 10000^(-i/32)),  [+32] = sin
__global__ void rope_table_kernel(float* tbl) {
    int t = blockIdx.x * 256 + threadIdx.x;   // 0..32767
    int s = t >> 5, iff = t & 31;
    float inv = expf(-(float)iff * 0.28782313662425576f);   // ln(10000)/32
    float ang = (float)s * inv;
    tbl[s * 64 + iff]      = cosf(ang);
    tbl[s * 64 + 32 + iff] = sinf(ang);
}

// RMSNorm: fp32 in, fp16 out (feeds GEMM A side)
__global__ void rmsnorm_kernel(const float* __restrict__ x,
                               const float* __restrict__ w,
                               __half* __restrict__ out) {
    int row = blockIdx.x;
    int tid = threadIdx.x;
    const float4 xv = ((const float4*)(x + (size_t)row * DD))[tid];
    float ss = xv.x*xv.x + xv.y*xv.y + xv.z*xv.z + xv.w*xv.w;
    #pragma unroll
    for (int o = 16; o; o >>= 1) ss += __shfl_xor_sync(0xffffffffu, ss, o);
    __shared__ float red[8];
    if ((tid & 31) == 0) red[tid >> 5] = ss;
    __syncthreads();
    if (tid < 32) {
        float v = (tid < 8) ? red[tid] : 0.f;
        #pragma unroll
        for (int o = 4; o; o >>= 1) v += __shfl_xor_sync(0xffffffffu, v, o);
        if (tid == 0) red[0] = v;
    }
    __syncthreads();
    float inv = rsqrtf(red[0] * (1.0f / DD) + 1e-6f);
    float4 wv = ((const float4*)w)[tid];
    __half2 h01 = __floats2half2_rn(xv.x * inv * wv.x, xv.y * inv * wv.y);
    __half2 h23 = __floats2half2_rn(xv.z * inv * wv.z, xv.w * inv * wv.w);
    uint2 o;
    o.x = *(uint32_t*)&h01;
    o.y = *(uint32_t*)&h23;
    ((uint2*)(out + (size_t)row * DD))[tid] = o;
}

// ---------------- fp16 tensor-core GEMM, 3-stage cp.async ------------------
// C = A @ W^T with per-z epilogue modes:
//   0: fp32 out (+bias/+res per template)
//   1: fp32 out, tf32-rounded (V)
//   2: rope: rotate pairs, emit fp16 hi/lo (q, k)
//   3: silu-fuse: out_half = C * silu(gate)  (up GEMM)

struct GemmArgs {
    const __half* w[3];
    const float* b[3];
    float* c[3];
    int mode[3];
    __half* chi[3];          // mode2 hi dst / mode3 half out
    __half* clo[3];          // mode2 lo dst
    const float* gate;       // mode3
    const float* tbl;        // mode2
};

#define HS_STR 40                         // halfs per smem row (80 B, pad 8)
#define HS_TILE (128 * HS_STR)            // halfs per stage per matrix
#define GEMM_SMEM (6 * HS_TILE * 2)       // 3 stages x (A+B) bytes = 61440
#define STG_STR 132                       // rope stage stride (floats)

template<bool HAS_BIAS, bool HAS_RES>
__global__ void __launch_bounds__(256)
gemm_f16(const __half* __restrict__ A, GemmArgs args,
         const float* __restrict__ res, int M, int N, int K) {
    const __half* __restrict__ W = args.w[blockIdx.z];
    const float* __restrict__ bias = args.b[blockIdx.z];
    float* __restrict__ C = args.c[blockIdx.z];
    const int mode = args.mode[blockIdx.z];

    extern __shared__ __half smh[];
    __half* Asb = smh;                    // 3 stages of [128][40]
    __half* Bsb = smh + 3 * HS_TILE;

    int bm = blockIdx.y, bn = blockIdx.x;
    int tid = threadIdx.x;
    int lane = tid & 31, warp = tid >> 5;
    int wm = (warp >> 2) * 64;
    int wn = (warp & 3) * 32;
    int r = lane >> 2, cq = lane & 3;

    float acc[4][4][4];
    #pragma unroll
    for (int i = 0; i < 4; i++)
        #pragma unroll
        for (int j = 0; j < 4; j++)
            #pragma unroll
            for (int t = 0; t < 4; t++) acc[i][j][t] = 0.f;

    const __half* Abase = A + (size_t)(bm * 128) * K;
    const __half* Wbase = W + (size_t)(bn * 128) * K;
    int lr = tid >> 2;
    int lc = (tid & 3) * 8;

    auto load_tile = [&](int st, int k0) {
        __half* As = Asb + st * HS_TILE;
        __half* Bs = Bsb + st * HS_TILE;
        #pragma unroll
        for (int i = 0; i < 2; i++) {
            int row = lr + 64 * i;
            cp16(&As[row * HS_STR + lc], Abase + (size_t)row * K + k0 + lc);
            cp16(&Bs[row * HS_STR + lc], Wbase + (size_t)row * K + k0 + lc);
        }
    };

    int nk = K >> 5;
    load_tile(0, 0);
    asm volatile("cp.async.commit_group;\n" ::);
    load_tile(1, 32);
    asm volatile("cp.async.commit_group;\n" ::);

    int a_row = lane & 15, a_col = (lane >> 4) * 8;
    int b_row = lane & 7,  b_col = ((lane >> 3) & 1) * 8;

    int s = 0;
    for (int kt = 0; kt < nk; kt++) {
        if (kt + 1 < nk) {
            asm volatile("cp.async.wait_group 1;\n" ::);
        } else {
            asm volatile("cp.async.wait_group 0;\n" ::);
        }
        __syncthreads();
        if (kt + 2 < nk) {
            int s2 = s + 2; if (s2 >= 3) s2 -= 3;
            load_tile(s2, (kt + 2) * 32);
            asm volatile("cp.async.commit_group;\n" ::);
        }

        const __half* As = Asb + s * HS_TILE;
        const __half* Bs = Bsb + s * HS_TILE;
        #pragma unroll
        for (int ks = 0; ks < 2; ks++) {
            int kb = ks * 16;
            uint32_t af[4][4], bf[4][2];
            #pragma unroll
            for (int mt = 0; mt < 4; mt++)
                ldmx4(af[mt], smem_u32(&As[(wm + mt * 16 + a_row) * HS_STR + kb + a_col]));
            #pragma unroll
            for (int nt = 0; nt < 4; nt++)
                ldmx2(bf[nt], smem_u32(&Bs[(wn + nt * 8 + b_row) * HS_STR + kb + b_col]));
            #pragma unroll
            for (int mt = 0; mt < 4; mt++)
                #pragma unroll
                for (int nt = 0; nt < 4; nt++)
                    mma16h(acc[mt][nt], af[mt], bf[nt]);
        }
        s = s + 1; if (s >= 3) s -= 3;
    }

    if (mode == 2) {
        // -------- rope epilogue: stage tile (+bias), rotate, emit hi/lo ----
        float* stage = (float*)smh;          // [64][STG_STR] = 33792 B
        __half* dhi = args.chi[blockIdx.z];
        __half* dlo = args.clo[blockIdx.z];
        const float* tbl = args.tbl;

        int lr2 = tid >> 2;                  // 0..63
        int cb  = (tid & 3) * 8;             // 0,8,16,24
        int m_g = bm * 128 + lr2;            // row for hp=0 (+64 for hp=1)

        #pragma unroll
        for (int hp = 0; hp < 2; hp++) {
            __syncthreads();
            if ((warp >> 2) == hp) {
                #pragma unroll
                for (int mt = 0; mt < 4; mt++) {
                    int lr0 = mt * 16 + r;
                    #pragma unroll
                    for (int nt = 0; nt < 4; nt++) {
                        int colL = wn + nt * 8 + 2 * cq;
                        float bx = 0.f, by = 0.f;
                        if (HAS_BIAS) {
                            float2 bb = *(const float2*)(bias + bn * 128 + colL);
                            bx = bb.x; by = bb.y;
                        }
                        stage[lr0 * STG_STR + colL]           = acc[mt][nt][0] + bx;
                        stage[lr0 * STG_STR + colL + 1]       = acc[mt][nt][1] + by;
                        stage[(lr0 + 8) * STG_STR + colL]     = acc[mt][nt][2] + bx;
                        stage[(lr0 + 8) * STG_STR + colL + 1] = acc[mt][nt][3] + by;
                    }
                }
            }
            __syncthreads();

            int m = m_g + hp * 64;
            int sp = m & (SS - 1);
            const float* trow = tbl + sp * 64;
            #pragma unroll
            for (int cg = 0; cg < 4; cg++) {
                int colb = cg * 32 + cb;          // 8 consecutive cols
                __align__(16) __half hh8[8];
                __align__(16) __half ll8[8];
                #pragma unroll
                for (int e = 0; e < 8; e++) {
                    int col = colb + e;
                    int iff = col & 31;
                    float cv = trow[iff];
                    float sv = trow[32 + iff];
                    float xv = stage[lr2 * STG_STR + col];
                    float xp = stage[lr2 * STG_STR + (col ^ 32)];
                    float y = (col & 32) ? (xv * cv + xp * sv)
                                         : (xv * cv - xp * sv);
                    __half hi = __float2half_rn(y);
                    hh8[e] = hi;
                    ll8[e] = __float2half_rn(y - __half2float(hi));
                }
                size_t go = (size_t)m * DD + bn * 128 + colb;
                *(uint4*)(dhi + go) = *(uint4*)hh8;
                *(uint4*)(dlo + go) = *(uint4*)ll8;
            }
        }
        return;
    }

    // -------- standard epilogue (modes 0/1/3) ------------------------------
    const bool do_rnd = (mode == 1);
    const bool do_silu = (mode == 3);
    __half* Ch = args.chi[blockIdx.z];
    const float* gate = args.gate;

    #pragma unroll
    for (int mt = 0; mt < 4; mt++) {
        int row0 = bm * 128 + wm + mt * 16 + r;
        #pragma unroll
        for (int nt = 0; nt < 4; nt++) {
            int col = bn * 128 + wn + nt * 8 + 2 * cq;
            float2 v0 = make_float2(acc[mt][nt][0], acc[mt][nt][1]);
            float2 v1 = make_float2(acc[mt][nt][2], acc[mt][nt][3]);
            if (HAS_BIAS) {
                float2 bb = *(const float2*)(bias + col);
                v0.x += bb.x; v0.y += bb.y; v1.x += bb.x; v1.y += bb.y;
            }
            size_t i0 = (size_t)row0 * N + col;
            size_t i1 = i0 + (size_t)8 * N;
            if (HAS_RES) {
                float2 r0 = *(const float2*)(res + i0);
                float2 r1 = *(const float2*)(res + i1);
                v0.x += r0.x; v0.y += r0.y; v1.x += r1.x; v1.y += r1.y;
            }
            if (do_silu) {
                float2 g0 = *(const float2*)(gate + i0);
                float2 g1 = *(const float2*)(gate + i1);
                v0.x *= g0.x / (1.f + expf(-g0.x));
                v0.y *= g0.y / (1.f + expf(-g0.y));
                v1.x *= g1.x / (1.f + expf(-g1.x));
                v1.y *= g1.y / (1.f + expf(-g1.y));
                *(__half2*)(Ch + i0) = __floats2half2_rn(v0.x, v0.y);
                *(__half2*)(Ch + i1) = __floats2half2_rn(v1.x, v1.y);
            } else {
                if (do_rnd) {
                    v0.x = rnd_tf32(v0.x); v0.y = rnd_tf32(v0.y);
                    v1.x = rnd_tf32(v1.x); v1.y = rnd_tf32(v1.y);
                }
                *(float2*)(C + i0) = v0;
                *(float2*)(C + i1) = v1;
            }
        }
    }
}

// ---------------- sliding-window attention (512 threads) -------------------
#define KQ_STR 72                        // halfs per q/k smem row (144 B)
#define AQ_STR 68                        // floats per V smem row
#define ASC_STR 321
#define OFF_QHI 0
#define OFF_QLO 9216
#define OFF_KV  18432
#define OFF_SC  55296
#define ATTN_SMEM (55296 + 64 * ASC_STR * 4)   // 137472

__global__ void __launch_bounds__(512)
attn_kernel(const __half* __restrict__ qhi_g, const __half* __restrict__ qlo_g,
            const __half* __restrict__ khi_g, const __half* __restrict__ klo_g,
            const float* __restrict__ v, __half* __restrict__ ao,
            float* __restrict__ attn_out) {
    extern __shared__ char smraw[];
    __half* Qhi = (__half*)(smraw + OFF_QHI);
    __half* Qlo = (__half*)(smraw + OFF_QLO);
    __half* Khi[2] = { (__half*)(smraw + OFF_KV),         (__half*)(smraw + OFF_KV + 18432) };
    __half* Klo[2] = { (__half*)(smraw + OFF_KV + 9216),  (__half*)(smraw + OFF_KV + 27648) };
    float*  Vb[2]  = { (float*)(smraw + OFF_KV),          (float*)(smraw + OFF_KV + 17408) };
    float* sc = (float*)(smraw + OFF_SC);

    int q0 = blockIdx.x * 64;
    int bh = blockIdx.y;
    int b  = bh >> 4, h = bh & 15;
    int tid = threadIdx.x;
    int lane = tid & 31, warp = tid >> 5;
    int wq = (warp & 3) * 16;
    int wn = (warp >> 2) * 16;
    int r = lane >> 2, cq = lane & 3;
    int a_row = lane & 15, a_col = (lane >> 4) * 8;
    int b_row = lane & 7,  b_col = ((lane >> 3) & 1) * 8;
    const float scale = 0.125f;

    const __half* khb = khi_g + (size_t)(b * SS) * DD + h * HDIM;
    const __half* klb = klo_g + (size_t)(b * SS) * DD + h * HDIM;
    const float*  vbase = v + (size_t)(b * SS) * DD + h * HDIM;

    {
        int qq = tid >> 3, dq = (tid & 7) * 8;
        const __half* qh = qhi_g + (size_t)(b * SS + q0 + qq) * DD + h * HDIM + dq;
        const __half* ql = qlo_g + (size_t)(b * SS + q0 + qq) * DD + h * HDIM + dq;
        cp16(&Qhi[qq * KQ_STR + dq], qh);
        cp16(&Qlo[qq * KQ_STR + dq], ql);
    }

    auto loadK = [&](int buf, int jb) {
        int kk = tid >> 3, dq = (tid & 7) * 8;
        int j = jb + kk;
        if (j >= 0) {
            cp16(&Khi[buf][kk * KQ_STR + dq], khb + (size_t)j * DD + dq);
            cp16(&Klo[buf][kk * KQ_STR + dq], klb + (size_t)j * DD + dq);
        } else {
            uint4 z = make_uint4(0, 0, 0, 0);
            *(uint4*)&Khi[buf][kk * KQ_STR + dq] = z;
            *(uint4*)&Klo[buf][kk * KQ_STR + dq] = z;
        }
    };

    // -------- Phase A: scores via fp16 hi/lo 3-product mma ----------------
    loadK(0, q0 - 256);
    asm volatile("cp.async.commit_group;\n" ::);
    for (int c = 0; c < 5; c++) {
        if (c < 4) {
            loadK((c + 1) & 1, q0 - 256 + (c + 1) * 64);
            asm volatile("cp.async.commit_group;\n" ::);
            asm volatile("cp.async.wait_group 1;\n" ::);
        } else {
            asm volatile("cp.async.wait_group 0;\n" ::);
        }
        __syncthreads();
        const __half* KH = Khi[c & 1];
        const __half* KL = Klo[c & 1];

        float acc[2][4];
        #pragma unroll
        for (int i = 0; i < 2; i++)
            #pragma unroll
            for (int j = 0; j < 4; j++) acc[i][j] = 0.f;

        #pragma unroll
        for (int ks = 0; ks < 4; ks++) {
            int kb = ks * 16;
            uint32_t ahi[4], alo[4];
            ldmx4(ahi, smem_u32(&Qhi[(wq + a_row) * KQ_STR + kb + a_col]));
            ldmx4(alo, smem_u32(&Qlo[(wq + a_row) * KQ_STR + kb + a_col]));
            #pragma unroll
            for (int nt = 0; nt < 2; nt++) {
                uint32_t bhi[2], blo[2];
                ldmx2(bhi, smem_u32(&KH[(wn + nt * 8 + b_row) * KQ_STR + kb + b_col]));
                ldmx2(blo, smem_u32(&KL[(wn + nt * 8 + b_row) * KQ_STR + kb + b_col]));
                mma16h(acc[nt], ahi, bhi);
                mma16h(acc[nt], ahi, blo);
                mma16h(acc[nt], alo, bhi);
            }
        }

        int jb = q0 - 256 + c * 64;
        #pragma unroll
        for (int nt = 0; nt < 2; nt++) {
            int jl = wn + nt * 8 + 2 * cq;
            #pragma unroll
            for (int u = 0; u < 2; u++) {
                int qq = wq + r + u * 8;
                int qi = q0 + qq;
                #pragma unroll
                for (int w2 = 0; w2 < 2; w2++) {
                    int jj = jb + jl + w2;
                    bool valid = (jj >= 0) && (jj <= qi) && (qi - jj < WIN);
                    sc[qq * ASC_STR + c * 64 + jl + w2] =
                        valid ? acc[nt][u * 2 + w2] * scale : -1e30f;
                }
            }
        }
        __syncthreads();
    }

    // -------- Phase B: softmax, 8 threads per row -------------------------
    {
        int qq = tid >> 3, g = tid & 7;
        float* row = sc + qq * ASC_STR;
        float mx = -1e30f;
        for (int s = g; s < 320; s += 8) mx = fmaxf(mx, row[s]);
        mx = fmaxf(mx, __shfl_xor_sync(0xffffffffu, mx, 1));
        mx = fmaxf(mx, __shfl_xor_sync(0xffffffffu, mx, 2));
        mx = fmaxf(mx, __shfl_xor_sync(0xffffffffu, mx, 4));
        float sum = 0.f;
        for (int s = g; s < 320; s += 8) {
            float e = expf(row[s] - mx);
            row[s] = e;
            sum += e;
        }
        sum += __shfl_xor_sync(0xffffffffu, sum, 1);
        sum += __shfl_xor_sync(0xffffffffu, sum, 2);
        sum += __shfl_xor_sync(0xffffffffu, sum, 4);
        float inv = 1.f / sum;
        for (int s = g; s < 320; s += 8) row[s] *= inv;
    }
    __syncthreads();

    // -------- Phase C: write full attn rows (zeros + probs) ---------------
    {
        int c4 = tid & 255;
        int half = tid >> 8;
        for (int it = 0; it < 32; it++) {
            int qq = it * 2 + half;
            int qi = q0 + qq;
            const float* src = sc + qq * ASC_STR;
            float rr[4];
            #pragma unroll
            for (int u = 0; u < 4; u++) {
                int j = c4 * 4 + u;
                bool in = (j <= qi) && (qi - j < WIN);
                rr[u] = in ? src[j - q0 + 256] : 0.f;
            }
            ((float4*)(attn_out + ((size_t)bh * SS + qi) * SS))[c4] =
                make_float4(rr[0], rr[1], rr[2], rr[3]);
        }
    }
    __syncthreads();

    // -------- Phase D: out = P @ V (tf32), double-buffered V ---------------
    float oacc[2][4];
    #pragma unroll
    for (int i = 0; i < 2; i++)
        #pragma unroll
        for (int j = 0; j < 4; j++) oacc[i][j] = 0.f;

    auto loadV = [&](int buf, int jb) {
        #pragma unroll
        for (int i = 0; i < 2; i++) {
            int ch = tid + 512 * i;
            int kk = ch >> 4, dq = (ch & 15) * 4;
            int j = jb + kk;
            if (j >= 0) cp16(&Vb[buf][kk * AQ_STR + dq], vbase + (size_t)j * DD + dq);
            else *(float4*)&Vb[buf][kk * AQ_STR + dq] = make_float4(0.f, 0.f, 0.f, 0.f);
        }
    };

    loadV(0, q0 - 256);
    asm volatile("cp.async.commit_group;\n" ::);
    for (int c = 0; c < 5; c++) {
        if (c < 4) {
            loadV((c + 1) & 1, q0 - 256 + (c + 1) * 64);
            asm volatile("cp.async.commit_group;\n" ::);
            asm volatile("cp.async.wait_group 1;\n" ::);
        } else {
            asm volatile("cp.async.wait_group 0;\n" ::);
        }
        __syncthreads();
        const float* Vs = Vb[c & 1];   // [kk][d]

        #pragma unroll
        for (int kb = 0; kb < 64; kb += 8) {
            uint32_t ah[4];
            ah[0] = f2tf32(sc[(wq + r)     * ASC_STR + c * 64 + kb + cq]);
            ah[1] = f2tf32(sc[(wq + r + 8) * ASC_STR + c * 64 + kb + cq]);
            ah[2] = f2tf32(sc[(wq + r)     * ASC_STR + c * 64 + kb + cq + 4]);
            ah[3] = f2tf32(sc[(wq + r + 8) * ASC_STR + c * 64 + kb + cq + 4]);
            #pragma unroll
            for (int nt = 0; nt < 2; nt++) {
                uint32_t bb[2];
                bb[0] = __float_as_uint(Vs[(kb + cq)     * AQ_STR + wn + nt * 8 + r]);
                bb[1] = __float_as_uint(Vs[(kb + cq + 4) * AQ_STR + wn + nt * 8 + r]);
                mma8(oacc[nt], ah, bb);
            }
        }
        __syncthreads();
    }

    #pragma unroll
    for (int nt = 0; nt < 2; nt++) {
        int d0 = wn + nt * 8 + 2 * cq;
        size_t b0 = ((size_t)(b * SS + q0 + wq + r))     * DD + h * HDIM + d0;
        size_t b1 = ((size_t)(b * SS + q0 + wq + r + 8)) * DD + h * HDIM + d0;
        __half2 h0 = __floats2half2_rn(oacc[nt][0], oacc[nt][1]);
        __half2 h1 = __floats2half2_rn(oacc[nt][2], oacc[nt][3]);
        *(__half2*)(ao + b0) = h0;
        *(__half2*)(ao + b1) = h1;
    }
}

// ---------------- launcher -------------------------------------------------
extern "C" void kernel_launch(void* const* d_in, const int* in_sizes, int n_in,
                              void* d_out, int out_size) {
    const float* x   = (const float*)d_in[0];
    const float* wq  = (const float*)d_in[1];
    const float* bq  = (const float*)d_in[2];
    const float* wk  = (const float*)d_in[3];
    const float* bk  = (const float*)d_in[4];
    const float* wv  = (const float*)d_in[5];
    const float* bv  = (const float*)d_in[6];
    const float* wo  = (const float*)d_in[7];
    const float* bo  = (const float*)d_in[8];
    const float* anw = (const float*)d_in[9];
    const float* fnw = (const float*)d_in[10];
    const float* gw  = (const float*)d_in[11];
    const float* uw  = (const float*)d_in[12];
    const float* dw  = (const float*)d_in[13];

    float* outx = (float*)d_out;                       // [B,S,D]
    float* outa = outx + (size_t)MR * DD;              // [B,H,S,S]

    float *p_v, *p_x1, *p_gate, *p_tbl;
    __half *p_hh, *p_h2h, *p_aoh, *p_acth, *p_wh;
    __half *p_qhi, *p_qlo, *p_khi, *p_klo;
    cudaGetSymbolAddress((void**)&p_v,    g_v);
    cudaGetSymbolAddress((void**)&p_x1,   g_x1);
    cudaGetSymbolAddress((void**)&p_gate, g_gate);
    cudaGetSymbolAddress((void**)&p_tbl,  g_tbl);
    cudaGetSymbolAddress((void**)&p_hh,   g_hh);
    cudaGetSymbolAddress((void**)&p_h2h,  g_h2h);
    cudaGetSymbolAddress((void**)&p_aoh,  g_aoh);
    cudaGetSymbolAddress((void**)&p_acth, g_acth);
    cudaGetSymbolAddress((void**)&p_wh,   g_wh);
    cudaGetSymbolAddress((void**)&p_qhi,  g_qhi);
    cudaGetSymbolAddress((void**)&p_qlo,  g_qlo);
    cudaGetSymbolAddress((void**)&p_khi,  g_khi);
    cudaGetSymbolAddress((void**)&p_klo,  g_klo);

    const size_t MB1 = 1024 * 1024;
    __half* hwq = p_wh;            __half* hwk = p_wh + 1 * MB1;
    __half* hwv = p_wh + 2 * MB1;  __half* hwo = p_wh + 3 * MB1;
    __half* hgw = p_wh + 4 * MB1;  __half* huw = p_wh + 8 * MB1;
    __half* hdw = p_wh + 12 * MB1;

    cudaFuncSetAttribute(attn_kernel,
                         cudaFuncAttributeMaxDynamicSharedMemorySize, ATTN_SMEM);
    cudaFuncSetAttribute(gemm_f16<true, false>,
                         cudaFuncAttributeMaxDynamicSharedMemorySize, GEMM_SMEM);
    cudaFuncSetAttribute(gemm_f16<true, true>,
                         cudaFuncAttributeMaxDynamicSharedMemorySize, GEMM_SMEM);
    cudaFuncSetAttribute(gemm_f16<false, false>,
                         cudaFuncAttributeMaxDynamicSharedMemorySize, GEMM_SMEM);
    cudaFuncSetAttribute(gemm_f16<false, true>,
                         cudaFuncAttributeMaxDynamicSharedMemorySize, GEMM_SMEM);

    // 0) weights -> fp16, rope table
    {
        WSet ws;
        ws.src[0] = (const float4*)wq; ws.dst[0] = hwq; ws.n4[0] = 262144;
        ws.src[1] = (const float4*)wk; ws.dst[1] = hwk; ws.n4[1] = 262144;
        ws.src[2] = (const float4*)wv; ws.dst[2] = hwv; ws.n4[2] = 262144;
        ws.src[3] = (const float4*)wo; ws.dst[3] = hwo; ws.n4[3] = 262144;
        ws.src[4] = (const float4*)gw; ws.dst[4] = hgw; ws.n4[4] = 1048576;
        ws.src[5] = (const float4*)uw; ws.dst[5] = huw; ws.n4[5] = 1048576;
        ws.src[6] = (const float4*)dw; ws.dst[6] = hdw; ws.n4[6] = 1048576;
        round_weights_kernel<<<dim3(4096, 7), 256>>>(ws);
    }
    rope_table_kernel<<<128, 256>>>(p_tbl);

    // 1) attn rmsnorm -> fp16
    rmsnorm_kernel<<<MR, 256>>>(x, anw, p_hh);

    // 2) QKV — z=3 launch: q,k rope->hi/lo; v tf32-rounded fp32
    {
        GemmArgs a = {};
        a.w[0] = hwq; a.w[1] = hwk; a.w[2] = hwv;
        a.b[0] = bq;  a.b[1] = bk;  a.b[2] = bv;
        a.c[0] = nullptr; a.c[1] = nullptr; a.c[2] = p_v;
        a.mode[0] = 2; a.mode[1] = 2; a.mode[2] = 1;
        a.chi[0] = p_qhi; a.clo[0] = p_qlo;
        a.chi[1] = p_khi; a.clo[1] = p_klo;
        a.tbl = p_tbl;
        gemm_f16<true, false><<<dim3(DD/128, MR/128, 3), 256, GEMM_SMEM>>>(
            p_hh, a, nullptr, MR, DD, DD);
    }
    // 3) attention (probs -> outa, context -> g_aoh fp16)
    attn_kernel<<<dim3(SS / 64, BB * HH), 512, ATTN_SMEM>>>(
        p_qhi, p_qlo, p_khi, p_klo, p_v, p_aoh, outa);
    // 4) O proj + bias + residual
    {
        GemmArgs a = {};
        a.w[0] = hwo; a.b[0] = bo; a.c[0] = p_x1; a.mode[0] = 0;
        gemm_f16<true, true><<<dim3(DD/128, MR/128, 1), 256, GEMM_SMEM>>>(
            p_aoh, a, x, MR, DD, DD);
    }
    // 5) ffn rmsnorm -> fp16
    rmsnorm_kernel<<<MR, 256>>>(p_x1, fnw, p_h2h);
    // 6) gate GEMM -> fp32
    {
        GemmArgs a = {};
        a.w[0] = hgw; a.c[0] = p_gate; a.mode[0] = 0;
        gemm_f16<false, false><<<dim3(FF/128, MR/128, 1), 256, GEMM_SMEM>>>(
            p_h2h, a, nullptr, MR, FF, DD);
    }
    // 7) up GEMM with fused silu(gate)*up -> fp16 act
    {
        GemmArgs a = {};
        a.w[0] = huw; a.mode[0] = 3;
        a.chi[0] = p_acth; a.gate = p_gate;
        gemm_f16<false, false><<<dim3(FF/128, MR/128, 1), 256, GEMM_SMEM>>>(
            p_h2h, a, nullptr, MR, FF, DD);
    }
    // 8) down + residual -> final x
    {
        GemmArgs a = {};
        a.w[0] = hdw; a.c[0] = outx; a.mode[0] = 0;
        gemm_f16<false, true><<<dim3(DD/128, MR/128, 1), 256, GEMM_SMEM>>>(
            p_acth, a, p_x1, MR, DD, FF);
    }
}

// round 13
// speedup vs baseline: 1.0067x; 1.0067x over previous
#include <cuda_runtime.h>
#include <cuda_fp16.h>
#include <cstdint>

// Problem constants
#define BB   2
#define SS   1024
#define DD   1024
#define HH   16
#define HDIM 64
#define WIN  256
#define FF   4096
#define MR   (BB*SS)   // 2048 rows

// ---------------- scratch (device globals; no allocation allowed) ----------
__device__ float  g_q   [MR*DD];
__device__ float  g_k   [MR*DD];
__device__ float  g_v   [MR*DD];
__device__ float  g_x1  [MR*DD];
__device__ float  g_gate[MR*FF];
__device__ __half g_hh  [MR*DD];    // rmsnorm1 out (fp16, GEMM A)
__device__ __half g_h2h [MR*DD];    // rmsnorm2 out
__device__ __half g_aoh [MR*DD];    // attn context out
__device__ __half g_acth[MR*FF];    // silu(gate)*up
__device__ __half g_qhi [MR*DD];
__device__ __half g_qlo [MR*DD];
__device__ __half g_khi [MR*DD];
__device__ __half g_klo [MR*DD];
__device__ __half g_wh  [16*1024*1024];  // fp16 weights: wq wk wv wo gw uw dw

// ---------------- common PTX helpers ---------------------------------------
__device__ __forceinline__ void cp16(void* smem_dst, const void* gsrc) {
    uint32_t s = (uint32_t)__cvta_generic_to_shared(smem_dst);
    asm volatile("cp.async.cg.shared.global [%0], [%1], 16;\n" :: "r"(s), "l"(gsrc));
}
__device__ __forceinline__ uint32_t f2tf32(float x) {
    uint32_t u;
    asm("cvt.rna.tf32.f32 %0, %1;" : "=r"(u) : "f"(x));
    return u;
}
__device__ __forceinline__ float rnd_tf32(float x) {
    return __uint_as_float(f2tf32(x));
}
__device__ __forceinline__ void mma8(float* d, const uint32_t* a, const uint32_t* b) {
    asm volatile(
        "mma.sync.aligned.m16n8k8.row.col.f32.tf32.tf32.f32 "
        "{%0,%1,%2,%3}, {%4,%5,%6,%7}, {%8,%9}, {%0,%1,%2,%3};\n"
        : "+f"(d[0]), "+f"(d[1]), "+f"(d[2]), "+f"(d[3])
        : "r"(a[0]), "r"(a[1]), "r"(a[2]), "r"(a[3]), "r"(b[0]), "r"(b[1]));
}
__device__ __forceinline__ void mma16h(float* d, const uint32_t* a, const uint32_t* b) {
    asm volatile(
        "mma.sync.aligned.m16n8k16.row.col.f32.f16.f16.f32 "
        "{%0,%1,%2,%3}, {%4,%5,%6,%7}, {%8,%9}, {%0,%1,%2,%3};\n"
        : "+f"(d[0]), "+f"(d[1]), "+f"(d[2]), "+f"(d[3])
        : "r"(a[0]), "r"(a[1]), "r"(a[2]), "r"(a[3]), "r"(b[0]), "r"(b[1]));
}
__device__ __forceinline__ void ldmx4(uint32_t* r, uint32_t addr) {
    asm volatile("ldmatrix.sync.aligned.m8n8.x4.shared.b16 {%0,%1,%2,%3}, [%4];"
                 : "=r"(r[0]), "=r"(r[1]), "=r"(r[2]), "=r"(r[3]) : "r"(addr));
}
__device__ __forceinline__ void ldmx2(uint32_t* r, uint32_t addr) {
    asm volatile("ldmatrix.sync.aligned.m8n8.x2.shared.b16 {%0,%1}, [%2];"
                 : "=r"(r[0]), "=r"(r[1]) : "r"(addr));
}
__device__ __forceinline__ uint32_t smem_u32(const void* p) {
    return (uint32_t)__cvta_generic_to_shared(p);
}

// ---------------- elementwise kernels ---------------------------------------
struct WSet {
    const float4* src[7];
    __half* dst[7];
    int n4[7];
};

__global__ void round_weights_kernel(WSet ws) {
    int reg = blockIdx.y;
    int i = blockIdx.x * 256 + threadIdx.x;
    if (i < ws.n4[reg]) {
        float4 v = ws.src[reg][i];
        __half2 h01 = __floats2half2_rn(v.x, v.y);
        __half2 h23 = __floats2half2_rn(v.z, v.w);
        uint2 o;
        o.x = *(uint32_t*)&h01;
        o.y = *(uint32_t*)&h23;
        ((uint2*)ws.dst[reg])[i] = o;
    }
}

// RMSNorm: fp32 in, fp16 out (feeds GEMM A side)
__global__ void rmsnorm_kernel(const float* __restrict__ x,
                               const float* __restrict__ w,
                               __half* __restrict__ out) {
    int row = blockIdx.x;
    int tid = threadIdx.x;
    const float4 xv = ((const float4*)(x + (size_t)row * DD))[tid];
    float ss = xv.x*xv.x + xv.y*xv.y + xv.z*xv.z + xv.w*xv.w;
    #pragma unroll
    for (int o = 16; o; o >>= 1) ss += __shfl_xor_sync(0xffffffffu, ss, o);
    __shared__ float red[8];
    if ((tid & 31) == 0) red[tid >> 5] = ss;
    __syncthreads();
    if (tid < 32) {
        float v = (tid < 8) ? red[tid] : 0.f;
        #pragma unroll
        for (int o = 4; o; o >>= 1) v += __shfl_xor_sync(0xffffffffu, v, o);
        if (tid == 0) red[0] = v;
    }
    __syncthreads();
    float inv = rsqrtf(red[0] * (1.0f / DD) + 1e-6f);
    float4 wv = ((const float4*)w)[tid];
    __half2 h01 = __floats2half2_rn(xv.x * inv * wv.x, xv.y * inv * wv.y);
    __half2 h23 = __floats2half2_rn(xv.z * inv * wv.z, xv.w * inv * wv.w);
    uint2 o;
    o.x = *(uint32_t*)&h01;
    o.y = *(uint32_t*)&h23;
    ((uint2*)(out + (size_t)row * DD))[tid] = o;
}

// RoPE: reads fp32 q/k, writes rotated values as fp16 hi/lo pairs
__global__ void rope_kernel(const float* __restrict__ q, const float* __restrict__ k,
                            __half* __restrict__ qhi, __half* __restrict__ qlo,
                            __half* __restrict__ khi, __half* __restrict__ klo) {
    int t = blockIdx.x * blockDim.x + threadIdx.x;
    int total = MR * 512;
    const float* p = (t < total) ? q : k;
    __half* ohi = (t < total) ? qhi : khi;
    __half* olo = (t < total) ? qlo : klo;
    int u = (t < total) ? t : (t - total);
    int m  = u >> 9;
    int pr = u & 511;
    int hh = pr >> 5;
    int i  = pr & 31;
    int s  = m & (SS - 1);
    float inv = expf(-(float)i * 0.28782313662425576f);   // ln(10000)/32
    float ang = (float)s * inv;
    float c = cosf(ang), sn = sinf(ang);
    size_t base = (size_t)m * DD + hh * HDIM + i;
    float x1 = p[base];
    float x2 = p[base + 32];
    float y1 = x1 * c - x2 * sn;
    float y2 = x2 * c + x1 * sn;
    __half h1 = __float2half_rn(y1);
    __half h2 = __float2half_rn(y2);
    __half l1 = __float2half_rn(y1 - __half2float(h1));
    __half l2 = __float2half_rn(y2 - __half2float(h2));
    ohi[base] = h1; ohi[base + 32] = h2;
    olo[base] = l1; olo[base + 32] = l2;
}

// ---------------- fp16 tensor-core GEMM, 3-stage cp.async ------------------
// C = A @ W^T. CTA tile (MT*32) x 128, 256 threads, 8 warps (2 x 4),
// warp tile (MT*16) x 32, mma.m16n8k16 fp32 accum, ldmatrix fragments.
// FUSE_SILU: out_half = C * silu(gate) (fp16); else fp32 out (+bias/res/rnd).

struct GemmArgs {
    const __half* w[3];
    const float* b[3];
    float* c[3];
    int rnd[3];              // tf32-round fp32 output (V)
    __half* ch[3];           // fp16 out for FUSE_SILU
    const float* gate;       // FUSE_SILU input
};

#define HS_STR 40                         // halfs per smem row (80 B, pad 8)

template<bool HAS_BIAS, bool HAS_RES, bool FUSE_SILU, int MT>
__global__ void __launch_bounds__(256)
gemm_f16(const __half* __restrict__ A, GemmArgs args,
         const float* __restrict__ res, int M, int N, int K) {
    constexpr int AROWS  = MT * 32;
    constexpr int ASTAGE = AROWS * HS_STR;
    constexpr int BSTAGE = 128 * HS_STR;

    const __half* __restrict__ W = args.w[blockIdx.z];
    const float* __restrict__ bias = args.b[blockIdx.z];
    float* __restrict__ C = args.c[blockIdx.z];
    const bool do_rnd = args.rnd[blockIdx.z] != 0;

    extern __shared__ __half smh[];
    __half* Asb = smh;                    // 3 stages of [AROWS][40]
    __half* Bsb = smh + 3 * ASTAGE;       // 3 stages of [128][40]

    int bm = blockIdx.y, bn = blockIdx.x;
    int tid = threadIdx.x;
    int lane = tid & 31, warp = tid >> 5;
    int wm = (warp >> 2) * (MT * 16);
    int wn = (warp & 3) * 32;
    int r = lane >> 2, cq = lane & 3;

    float acc[MT][4][4];
    #pragma unroll
    for (int i = 0; i < MT; i++)
        #pragma unroll
        for (int j = 0; j < 4; j++)
            #pragma unroll
            for (int t = 0; t < 4; t++) acc[i][j][t] = 0.f;

    const __half* Abase = A + (size_t)(bm * AROWS) * K;
    const __half* Wbase = W + (size_t)(bn * 128) * K;
    int lr = tid >> 2;
    int lc = (tid & 3) * 8;

    auto load_tile = [&](int st, int k0) {
        __half* As = Asb + st * ASTAGE;
        __half* Bs = Bsb + st * BSTAGE;
        #pragma unroll
        for (int i = 0; i < MT / 2; i++) {
            int row = lr + 64 * i;
            cp16(&As[row * HS_STR + lc], Abase + (size_t)row * K + k0 + lc);
        }
        #pragma unroll
        for (int i = 0; i < 2; i++) {
            int row = lr + 64 * i;
            cp16(&Bs[row * HS_STR + lc], Wbase + (size_t)row * K + k0 + lc);
        }
    };

    int nk = K >> 5;
    load_tile(0, 0);
    asm volatile("cp.async.commit_group;\n" ::);
    load_tile(1, 32);
    asm volatile("cp.async.commit_group;\n" ::);

    int a_row = lane & 15, a_col = (lane >> 4) * 8;
    int b_row = lane & 7,  b_col = ((lane >> 3) & 1) * 8;

    int s = 0;
    for (int kt = 0; kt < nk; kt++) {
        if (kt + 1 < nk) {
            asm volatile("cp.async.wait_group 1;\n" ::);
        } else {
            asm volatile("cp.async.wait_group 0;\n" ::);
        }
        __syncthreads();
        if (kt + 2 < nk) {
            int s2 = s + 2; if (s2 >= 3) s2 -= 3;
            load_tile(s2, (kt + 2) * 32);
            asm volatile("cp.async.commit_group;\n" ::);
        }

        const __half* As = Asb + s * ASTAGE;
        const __half* Bs = Bsb + s * BSTAGE;
        #pragma unroll
        for (int ks = 0; ks < 2; ks++) {
            int kb = ks * 16;
            uint32_t af[MT][4], bf[4][2];
            #pragma unroll
            for (int mt = 0; mt < MT; mt++)
                ldmx4(af[mt], smem_u32(&As[(wm + mt * 16 + a_row) * HS_STR + kb + a_col]));
            #pragma unroll
            for (int nt = 0; nt < 4; nt++)
                ldmx2(bf[nt], smem_u32(&Bs[(wn + nt * 8 + b_row) * HS_STR + kb + b_col]));
            #pragma unroll
            for (int mt = 0; mt < MT; mt++)
                #pragma unroll
                for (int nt = 0; nt < 4; nt++)
                    mma16h(acc[mt][nt], af[mt], bf[nt]);
        }
        s = s + 1; if (s >= 3) s -= 3;
    }

    // epilogue
    __half* Ch = args.ch[blockIdx.z];
    const float* gate = args.gate;

    #pragma unroll
    for (int mt = 0; mt < MT; mt++) {
        int row0 = bm * AROWS + wm + mt * 16 + r;
        #pragma unroll
        for (int nt = 0; nt < 4; nt++) {
            int col = bn * 128 + wn + nt * 8 + 2 * cq;
            float2 v0 = make_float2(acc[mt][nt][0], acc[mt][nt][1]);
            float2 v1 = make_float2(acc[mt][nt][2], acc[mt][nt][3]);
            if (HAS_BIAS) {
                float2 bb = *(const float2*)(bias + col);
                v0.x += bb.x; v0.y += bb.y; v1.x += bb.x; v1.y += bb.y;
            }
            size_t i0 = (size_t)row0 * N + col;
            size_t i1 = i0 + (size_t)8 * N;
            if (HAS_RES) {
                float2 r0 = *(const float2*)(res + i0);
                float2 r1 = *(const float2*)(res + i1);
                v0.x += r0.x; v0.y += r0.y; v1.x += r1.x; v1.y += r1.y;
            }
            if (FUSE_SILU) {
                float2 g0 = *(const float2*)(gate + i0);
                float2 g1 = *(const float2*)(gate + i1);
                v0.x *= g0.x / (1.f + expf(-g0.x));
                v0.y *= g0.y / (1.f + expf(-g0.y));
                v1.x *= g1.x / (1.f + expf(-g1.x));
                v1.y *= g1.y / (1.f + expf(-g1.y));
                *(__half2*)(Ch + i0) = __floats2half2_rn(v0.x, v0.y);
                *(__half2*)(Ch + i1) = __floats2half2_rn(v1.x, v1.y);
            } else {
                if (do_rnd) {
                    v0.x = rnd_tf32(v0.x); v0.y = rnd_tf32(v0.y);
                    v1.x = rnd_tf32(v1.x); v1.y = rnd_tf32(v1.y);
                }
                *(float2*)(C + i0) = v0;
                *(float2*)(C + i1) = v1;
            }
        }
    }
}

#define GSMEM_MT4 ((3 * 128 * HS_STR + 3 * 128 * HS_STR) * 2)   // 61440
#define GSMEM_MT2 ((3 * 64  * HS_STR + 3 * 128 * HS_STR) * 2)   // 46080

// ---------------- sliding-window attention (512 threads) -------------------
#define KQ_STR 72                        // halfs per q/k smem row (144 B)
#define AQ_STR 68                        // floats per V smem row
#define ASC_STR 321
#define OFF_QHI 0
#define OFF_QLO 9216
#define OFF_KV  18432
#define OFF_SC  55296
#define ATTN_SMEM (55296 + 64 * ASC_STR * 4)   // 137472

__global__ void __launch_bounds__(512)
attn_kernel(const __half* __restrict__ qhi_g, const __half* __restrict__ qlo_g,
            const __half* __restrict__ khi_g, const __half* __restrict__ klo_g,
            const float* __restrict__ v, __half* __restrict__ ao,
            float* __restrict__ attn_out) {
    extern __shared__ char smraw[];
    __half* Qhi = (__half*)(smraw + OFF_QHI);
    __half* Qlo = (__half*)(smraw + OFF_QLO);
    __half* Khi[2] = { (__half*)(smraw + OFF_KV),         (__half*)(smraw + OFF_KV + 18432) };
    __half* Klo[2] = { (__half*)(smraw + OFF_KV + 9216),  (__half*)(smraw + OFF_KV + 27648) };
    float*  Vb[2]  = { (float*)(smraw + OFF_KV),          (float*)(smraw + OFF_KV + 17408) };
    float* sc = (float*)(smraw + OFF_SC);

    int q0 = blockIdx.x * 64;
    int bh = blockIdx.y;
    int b  = bh >> 4, h = bh & 15;
    int tid = threadIdx.x;
    int lane = tid & 31, warp = tid >> 5;
    int wq = (warp & 3) * 16;
    int wn = (warp >> 2) * 16;
    int r = lane >> 2, cq = lane & 3;
    int a_row = lane & 15, a_col = (lane >> 4) * 8;
    int b_row = lane & 7,  b_col = ((lane >> 3) & 1) * 8;
    const float scale = 0.125f;

    const __half* khb = khi_g + (size_t)(b * SS) * DD + h * HDIM;
    const __half* klb = klo_g + (size_t)(b * SS) * DD + h * HDIM;
    const float*  vbase = v + (size_t)(b * SS) * DD + h * HDIM;

    {
        int qq = tid >> 3, dq = (tid & 7) * 8;
        const __half* qh = qhi_g + (size_t)(b * SS + q0 + qq) * DD + h * HDIM + dq;
        const __half* ql = qlo_g + (size_t)(b * SS + q0 + qq) * DD + h * HDIM + dq;
        cp16(&Qhi[qq * KQ_STR + dq], qh);
        cp16(&Qlo[qq * KQ_STR + dq], ql);
    }

    auto loadK = [&](int buf, int jb) {
        int kk = tid >> 3, dq = (tid & 7) * 8;
        int j = jb + kk;
        if (j >= 0) {
            cp16(&Khi[buf][kk * KQ_STR + dq], khb + (size_t)j * DD + dq);
            cp16(&Klo[buf][kk * KQ_STR + dq], klb + (size_t)j * DD + dq);
        } else {
            uint4 z = make_uint4(0, 0, 0, 0);
            *(uint4*)&Khi[buf][kk * KQ_STR + dq] = z;
            *(uint4*)&Klo[buf][kk * KQ_STR + dq] = z;
        }
    };

    // -------- Phase A: scores via fp16 hi/lo 3-product mma ----------------
    loadK(0, q0 - 256);
    asm volatile("cp.async.commit_group;\n" ::);
    for (int c = 0; c < 5; c++) {
        if (c < 4) {
            loadK((c + 1) & 1, q0 - 256 + (c + 1) * 64);
            asm volatile("cp.async.commit_group;\n" ::);
            asm volatile("cp.async.wait_group 1;\n" ::);
        } else {
            asm volatile("cp.async.wait_group 0;\n" ::);
        }
        __syncthreads();
        const __half* KH = Khi[c & 1];
        const __half* KL = Klo[c & 1];

        float acc[2][4];
        #pragma unroll
        for (int i = 0; i < 2; i++)
            #pragma unroll
            for (int j = 0; j < 4; j++) acc[i][j] = 0.f;

        #pragma unroll
        for (int ks = 0; ks < 4; ks++) {
            int kb = ks * 16;
            uint32_t ahi[4], alo[4];
            ldmx4(ahi, smem_u32(&Qhi[(wq + a_row) * KQ_STR + kb + a_col]));
            ldmx4(alo, smem_u32(&Qlo[(wq + a_row) * KQ_STR + kb + a_col]));
            #pragma unroll
            for (int nt = 0; nt < 2; nt++) {
                uint32_t bhi[2], blo[2];
                ldmx2(bhi, smem_u32(&KH[(wn + nt * 8 + b_row) * KQ_STR + kb + b_col]));
                ldmx2(blo, smem_u32(&KL[(wn + nt * 8 + b_row) * KQ_STR + kb + b_col]));
                mma16h(acc[nt], ahi, bhi);
                mma16h(acc[nt], ahi, blo);
                mma16h(acc[nt], alo, bhi);
            }
        }

        int jb = q0 - 256 + c * 64;
        #pragma unroll
        for (int nt = 0; nt < 2; nt++) {
            int jl = wn + nt * 8 + 2 * cq;
            #pragma unroll
            for (int u = 0; u < 2; u++) {
                int qq = wq + r + u * 8;
                int qi = q0 + qq;
                #pragma unroll
                for (int w2 = 0; w2 < 2; w2++) {
                    int jj = jb + jl + w2;
                    bool valid = (jj >= 0) && (jj <= qi) && (qi - jj < WIN);
                    sc[qq * ASC_STR + c * 64 + jl + w2] =
                        valid ? acc[nt][u * 2 + w2] * scale : -1e30f;
                }
            }
        }
        __syncthreads();
    }

    // -------- Phase B: softmax, 8 threads per row -------------------------
    {
        int qq = tid >> 3, g = tid & 7;
        float* row = sc + qq * ASC_STR;
        float mx = -1e30f;
        for (int s = g; s < 320; s += 8) mx = fmaxf(mx, row[s]);
        mx = fmaxf(mx, __shfl_xor_sync(0xffffffffu, mx, 1));
        mx = fmaxf(mx, __shfl_xor_sync(0xffffffffu, mx, 2));
        mx = fmaxf(mx, __shfl_xor_sync(0xffffffffu, mx, 4));
        float sum = 0.f;
        for (int s = g; s < 320; s += 8) {
            float e = expf(row[s] - mx);
            row[s] = e;
            sum += e;
        }
        sum += __shfl_xor_sync(0xffffffffu, sum, 1);
        sum += __shfl_xor_sync(0xffffffffu, sum, 2);
        sum += __shfl_xor_sync(0xffffffffu, sum, 4);
        float inv = 1.f / sum;
        for (int s = g; s < 320; s += 8) row[s] *= inv;
    }
    __syncthreads();

    // -------- Phase C: write full attn rows (zeros + probs) ---------------
    {
        int c4 = tid & 255;
        int half = tid >> 8;
        for (int it = 0; it < 32; it++) {
            int qq = it * 2 + half;
            int qi = q0 + qq;
            const float* src = sc + qq * ASC_STR;
            float rr[4];
            #pragma unroll
            for (int u = 0; u < 4; u++) {
                int j = c4 * 4 + u;
                bool in = (j <= qi) && (qi - j < WIN);
                rr[u] = in ? src[j - q0 + 256] : 0.f;
            }
            ((float4*)(attn_out + ((size_t)bh * SS + qi) * SS))[c4] =
                make_float4(rr[0], rr[1], rr[2], rr[3]);
        }
    }
    __syncthreads();

    // -------- Phase D: out = P @ V (tf32), double-buffered V ---------------
    float oacc[2][4];
    #pragma unroll
    for (int i = 0; i < 2; i++)
        #pragma unroll
        for (int j = 0; j < 4; j++) oacc[i][j] = 0.f;

    auto loadV = [&](int buf, int jb) {
        #pragma unroll
        for (int i = 0; i < 2; i++) {
            int ch = tid + 512 * i;
            int kk = ch >> 4, dq = (ch & 15) * 4;
            int j = jb + kk;
            if (j >= 0) cp16(&Vb[buf][kk * AQ_STR + dq], vbase + (size_t)j * DD + dq);
            else *(float4*)&Vb[buf][kk * AQ_STR + dq] = make_float4(0.f, 0.f, 0.f, 0.f);
        }
    };

    loadV(0, q0 - 256);
    asm volatile("cp.async.commit_group;\n" ::);
    for (int c = 0; c < 5; c++) {
        if (c < 4) {
            loadV((c + 1) & 1, q0 - 256 + (c + 1) * 64);
            asm volatile("cp.async.commit_group;\n" ::);
            asm volatile("cp.async.wait_group 1;\n" ::);
        } else {
            asm volatile("cp.async.wait_group 0;\n" ::);
        }
        __syncthreads();
        const float* Vs = Vb[c & 1];   // [kk][d]

        #pragma unroll
        for (int kb = 0; kb < 64; kb += 8) {
            uint32_t ah[4];
            ah[0] = f2tf32(sc[(wq + r)     * ASC_STR + c * 64 + kb + cq]);
            ah[1] = f2tf32(sc[(wq + r + 8) * ASC_STR + c * 64 + kb + cq]);
            ah[2] = f2tf32(sc[(wq + r)     * ASC_STR + c * 64 + kb + cq + 4]);
            ah[3] = f2tf32(sc[(wq + r + 8) * ASC_STR + c * 64 + kb + cq + 4]);
            #pragma unroll
            for (int nt = 0; nt < 2; nt++) {
                uint32_t bb[2];
                bb[0] = __float_as_uint(Vs[(kb + cq)     * AQ_STR + wn + nt * 8 + r]);
                bb[1] = __float_as_uint(Vs[(kb + cq + 4) * AQ_STR + wn + nt * 8 + r]);
                mma8(oacc[nt], ah, bb);
            }
        }
        __syncthreads();
    }

    #pragma unroll
    for (int nt = 0; nt < 2; nt++) {
        int d0 = wn + nt * 8 + 2 * cq;
        size_t b0 = ((size_t)(b * SS + q0 + wq + r))     * DD + h * HDIM + d0;
        size_t b1 = ((size_t)(b * SS + q0 + wq + r + 8)) * DD + h * HDIM + d0;
        __half2 h0 = __floats2half2_rn(oacc[nt][0], oacc[nt][1]);
        __half2 h1 = __floats2half2_rn(oacc[nt][2], oacc[nt][3]);
        *(__half2*)(ao + b0) = h0;
        *(__half2*)(ao + b1) = h1;
    }
}

// ---------------- launcher -------------------------------------------------
extern "C" void kernel_launch(void* const* d_in, const int* in_sizes, int n_in,
                              void* d_out, int out_size) {
    const float* x   = (const float*)d_in[0];
    const float* wq  = (const float*)d_in[1];
    const float* bq  = (const float*)d_in[2];
    const float* wk  = (const float*)d_in[3];
    const float* bk  = (const float*)d_in[4];
    const float* wv  = (const float*)d_in[5];
    const float* bv  = (const float*)d_in[6];
    const float* wo  = (const float*)d_in[7];
    const float* bo  = (const float*)d_in[8];
    const float* anw = (const float*)d_in[9];
    const float* fnw = (const float*)d_in[10];
    const float* gw  = (const float*)d_in[11];
    const float* uw  = (const float*)d_in[12];
    const float* dw  = (const float*)d_in[13];

    float* outx = (float*)d_out;                       // [B,S,D]
    float* outa = outx + (size_t)MR * DD;              // [B,H,S,S]

    float *p_q, *p_k, *p_v, *p_x1, *p_gate;
    __half *p_hh, *p_h2h, *p_aoh, *p_acth, *p_wh;
    __half *p_qhi, *p_qlo, *p_khi, *p_klo;
    cudaGetSymbolAddress((void**)&p_q,    g_q);
    cudaGetSymbolAddress((void**)&p_k,    g_k);
    cudaGetSymbolAddress((void**)&p_v,    g_v);
    cudaGetSymbolAddress((void**)&p_x1,   g_x1);
    cudaGetSymbolAddress((void**)&p_gate, g_gate);
    cudaGetSymbolAddress((void**)&p_hh,   g_hh);
    cudaGetSymbolAddress((void**)&p_h2h,  g_h2h);
    cudaGetSymbolAddress((void**)&p_aoh,  g_aoh);
    cudaGetSymbolAddress((void**)&p_acth, g_acth);
    cudaGetSymbolAddress((void**)&p_wh,   g_wh);
    cudaGetSymbolAddress((void**)&p_qhi,  g_qhi);
    cudaGetSymbolAddress((void**)&p_qlo,  g_qlo);
    cudaGetSymbolAddress((void**)&p_khi,  g_khi);
    cudaGetSymbolAddress((void**)&p_klo,  g_klo);

    const size_t MB1 = 1024 * 1024;
    __half* hwq = p_wh;            __half* hwk = p_wh + 1 * MB1;
    __half* hwv = p_wh + 2 * MB1;  __half* hwo = p_wh + 3 * MB1;
    __half* hgw = p_wh + 4 * MB1;  __half* huw = p_wh + 8 * MB1;
    __half* hdw = p_wh + 12 * MB1;

    cudaFuncSetAttribute(attn_kernel,
                         cudaFuncAttributeMaxDynamicSharedMemorySize, ATTN_SMEM);
    cudaFuncSetAttribute(gemm_f16<true, false, false, 4>,
                         cudaFuncAttributeMaxDynamicSharedMemorySize, GSMEM_MT4);
    cudaFuncSetAttribute(gemm_f16<false, false, false, 4>,
                         cudaFuncAttributeMaxDynamicSharedMemorySize, GSMEM_MT4);
    cudaFuncSetAttribute(gemm_f16<false, false, true, 4>,
                         cudaFuncAttributeMaxDynamicSharedMemorySize, GSMEM_MT4);
    cudaFuncSetAttribute(gemm_f16<true, true, false, 2>,
                         cudaFuncAttributeMaxDynamicSharedMemorySize, GSMEM_MT2);
    cudaFuncSetAttribute(gemm_f16<false, true, false, 2>,
                         cudaFuncAttributeMaxDynamicSharedMemorySize, GSMEM_MT2);

    // 0) weights -> fp16 in one launch
    {
        WSet ws;
        ws.src[0] = (const float4*)wq; ws.dst[0] = hwq; ws.n4[0] = 262144;
        ws.src[1] = (const float4*)wk; ws.dst[1] = hwk; ws.n4[1] = 262144;
        ws.src[2] = (const float4*)wv; ws.dst[2] = hwv; ws.n4[2] = 262144;
        ws.src[3] = (const float4*)wo; ws.dst[3] = hwo; ws.n4[3] = 262144;
        ws.src[4] = (const float4*)gw; ws.dst[4] = hgw; ws.n4[4] = 1048576;
        ws.src[5] = (const float4*)uw; ws.dst[5] = huw; ws.n4[5] = 1048576;
        ws.src[6] = (const float4*)dw; ws.dst[6] = hdw; ws.n4[6] = 1048576;
        round_weights_kernel<<<dim3(4096, 7), 256>>>(ws);
    }

    // 1) attn rmsnorm -> fp16
    rmsnorm_kernel<<<MR, 256>>>(x, anw, p_hh);

    // 2) QKV — one z=3 fp16 launch; V tf32-rounded in epilogue
    {
        GemmArgs a = {};
        a.w[0] = hwq; a.w[1] = hwk; a.w[2] = hwv;
        a.b[0] = bq;  a.b[1] = bk;  a.b[2] = bv;
        a.c[0] = p_q; a.c[1] = p_k; a.c[2] = p_v;
        a.rnd[0] = 0; a.rnd[1] = 0; a.rnd[2] = 1;
        gemm_f16<true, false, false, 4><<<dim3(DD/128, MR/128, 3), 256, GSMEM_MT4>>>(
            p_hh, a, nullptr, MR, DD, DD);
    }
    // 3) RoPE -> fp16 hi/lo arrays
    rope_kernel<<<(2 * MR * 512) / 256, 256>>>(p_q, p_k, p_qhi, p_qlo, p_khi, p_klo);
    // 4) attention (probs -> outa, context -> g_aoh fp16)
    attn_kernel<<<dim3(SS / 64, BB * HH), 512, ATTN_SMEM>>>(
        p_qhi, p_qlo, p_khi, p_klo, p_v, p_aoh, outa);
    // 5) O proj + bias + residual  (MT=2: 256 CTAs -> full wave)
    {
        GemmArgs a = {};
        a.w[0] = hwo; a.b[0] = bo; a.c[0] = p_x1;
        gemm_f16<true, true, false, 2><<<dim3(DD/128, MR/64, 1), 256, GSMEM_MT2>>>(
            p_aoh, a, x, MR, DD, DD);
    }
    // 6) ffn rmsnorm -> fp16
    rmsnorm_kernel<<<MR, 256>>>(p_x1, fnw, p_h2h);
    // 7) gate GEMM -> fp32
    {
        GemmArgs a = {};
        a.w[0] = hgw; a.c[0] = p_gate;
        gemm_f16<false, false, false, 4><<<dim3(FF/128, MR/128, 1), 256, GSMEM_MT4>>>(
            p_h2h, a, nullptr, MR, FF, DD);
    }
    // 8) up GEMM with fused silu(gate)*up -> fp16 act
    {
        GemmArgs a = {};
        a.w[0] = huw;
        a.ch[0] = p_acth; a.gate = p_gate;
        gemm_f16<false, false, true, 4><<<dim3(FF/128, MR/128, 1), 256, GSMEM_MT4>>>(
            p_h2h, a, nullptr, MR, FF, DD);
    }
    // 9) down + residual -> final x  (MT=2: 256 CTAs -> full wave)
    {
        GemmArgs a = {};
        a.w[0] = hdw; a.c[0] = outx;
        gemm_f16<false, true, false, 2><<<dim3(DD/128, MR/64, 1), 256, GSMEM_MT2>>>(
            p_acth, a, p_x1, MR, DD, FF);
    }
}

// round 14
// speedup vs baseline: 1.0479x; 1.0409x over previous
#include <cuda_runtime.h>
#include <cuda_fp16.h>
#include <cstdint>

// Problem constants
#define BB   2
#define SS   1024
#define DD   1024
#define HH   16
#define HDIM 64
#define WIN  256
#define FF   4096
#define MR   (BB*SS)   // 2048 rows

// ---------------- scratch (device globals; no allocation allowed) ----------
__device__ float  g_q   [MR*DD];
__device__ float  g_k   [MR*DD];
__device__ float  g_v   [MR*DD];
__device__ float  g_x1  [MR*DD];
__device__ float  g_gate[MR*FF];
__device__ float  g_up  [MR*FF];
__device__ __half g_hh  [MR*DD];    // rmsnorm1 out (fp16, GEMM A)
__device__ __half g_h2h [MR*DD];    // rmsnorm2 out
__device__ __half g_aoh [MR*DD];    // attn context out
__device__ __half g_acth[MR*FF];    // silu(gate)*up
__device__ __half g_qhi [MR*DD];
__device__ __half g_qlo [MR*DD];
__device__ __half g_khi [MR*DD];
__device__ __half g_klo [MR*DD];
__device__ __half g_wh  [16*1024*1024];  // fp16 weights: wq wk wv wo gw uw dw

// ---------------- common PTX helpers ---------------------------------------
__device__ __forceinline__ void cp16(void* smem_dst, const void* gsrc) {
    uint32_t s = (uint32_t)__cvta_generic_to_shared(smem_dst);
    asm volatile("cp.async.cg.shared.global [%0], [%1], 16;\n" :: "r"(s), "l"(gsrc));
}
__device__ __forceinline__ uint32_t f2tf32(float x) {
    uint32_t u;
    asm("cvt.rna.tf32.f32 %0, %1;" : "=r"(u) : "f"(x));
    return u;
}
__device__ __forceinline__ float rnd_tf32(float x) {
    return __uint_as_float(f2tf32(x));
}
__device__ __forceinline__ void mma8(float* d, const uint32_t* a, const uint32_t* b) {
    asm volatile(
        "mma.sync.aligned.m16n8k8.row.col.f32.tf32.tf32.f32 "
        "{%0,%1,%2,%3}, {%4,%5,%6,%7}, {%8,%9}, {%0,%1,%2,%3};\n"
        : "+f"(d[0]), "+f"(d[1]), "+f"(d[2]), "+f"(d[3])
        : "r"(a[0]), "r"(a[1]), "r"(a[2]), "r"(a[3]), "r"(b[0]), "r"(b[1]));
}
__device__ __forceinline__ void mma16h(float* d, const uint32_t* a, const uint32_t* b) {
    asm volatile(
        "mma.sync.aligned.m16n8k16.row.col.f32.f16.f16.f32 "
        "{%0,%1,%2,%3}, {%4,%5,%6,%7}, {%8,%9}, {%0,%1,%2,%3};\n"
        : "+f"(d[0]), "+f"(d[1]), "+f"(d[2]), "+f"(d[3])
        : "r"(a[0]), "r"(a[1]), "r"(a[2]), "r"(a[3]), "r"(b[0]), "r"(b[1]));
}
__device__ __forceinline__ void ldmx4(uint32_t* r, uint32_t addr) {
    asm volatile("ldmatrix.sync.aligned.m8n8.x4.shared.b16 {%0,%1,%2,%3}, [%4];"
                 : "=r"(r[0]), "=r"(r[1]), "=r"(r[2]), "=r"(r[3]) : "r"(addr));
}
__device__ __forceinline__ void ldmx2(uint32_t* r, uint32_t addr) {
    asm volatile("ldmatrix.sync.aligned.m8n8.x2.shared.b16 {%0,%1}, [%2];"
                 : "=r"(r[0]), "=r"(r[1]) : "r"(addr));
}
__device__ __forceinline__ uint32_t smem_u32(const void* p) {
    return (uint32_t)__cvta_generic_to_shared(p);
}

// ---------------- elementwise kernels ---------------------------------------
struct WSet {
    const float4* src[7];
    __half* dst[7];
    int n4[7];
};

__global__ void round_weights_kernel(WSet ws) {
    int reg = blockIdx.y;
    int i = blockIdx.x * 256 + threadIdx.x;
    if (i < ws.n4[reg]) {
        float4 v = ws.src[reg][i];
        __half2 h01 = __floats2half2_rn(v.x, v.y);
        __half2 h23 = __floats2half2_rn(v.z, v.w);
        uint2 o;
        o.x = *(uint32_t*)&h01;
        o.y = *(uint32_t*)&h23;
        ((uint2*)ws.dst[reg])[i] = o;
    }
}

// RMSNorm: fp32 in, fp16 out (feeds GEMM A side)
__global__ void rmsnorm_kernel(const float* __restrict__ x,
                               const float* __restrict__ w,
                               __half* __restrict__ out) {
    int row = blockIdx.x;
    int tid = threadIdx.x;
    const float4 xv = ((const float4*)(x + (size_t)row * DD))[tid];
    float ss = xv.x*xv.x + xv.y*xv.y + xv.z*xv.z + xv.w*xv.w;
    #pragma unroll
    for (int o = 16; o; o >>= 1) ss += __shfl_xor_sync(0xffffffffu, ss, o);
    __shared__ float red[8];
    if ((tid & 31) == 0) red[tid >> 5] = ss;
    __syncthreads();
    if (tid < 32) {
        float v = (tid < 8) ? red[tid] : 0.f;
        #pragma unroll
        for (int o = 4; o; o >>= 1) v += __shfl_xor_sync(0xffffffffu, v, o);
        if (tid == 0) red[0] = v;
    }
    __syncthreads();
    float inv = rsqrtf(red[0] * (1.0f / DD) + 1e-6f);
    float4 wv = ((const float4*)w)[tid];
    __half2 h01 = __floats2half2_rn(xv.x * inv * wv.x, xv.y * inv * wv.y);
    __half2 h23 = __floats2half2_rn(xv.z * inv * wv.z, xv.w * inv * wv.w);
    uint2 o;
    o.x = *(uint32_t*)&h01;
    o.y = *(uint32_t*)&h23;
    ((uint2*)(out + (size_t)row * DD))[tid] = o;
}

// RoPE: reads fp32 q/k, writes rotated values as fp16 hi/lo pairs
__global__ void rope_kernel(const float* __restrict__ q, const float* __restrict__ k,
                            __half* __restrict__ qhi, __half* __restrict__ qlo,
                            __half* __restrict__ khi, __half* __restrict__ klo) {
    int t = blockIdx.x * blockDim.x + threadIdx.x;
    int total = MR * 512;
    const float* p = (t < total) ? q : k;
    __half* ohi = (t < total) ? qhi : khi;
    __half* olo = (t < total) ? qlo : klo;
    int u = (t < total) ? t : (t - total);
    int m  = u >> 9;
    int pr = u & 511;
    int hh = pr >> 5;
    int i  = pr & 31;
    int s  = m & (SS - 1);
    float inv = expf(-(float)i * 0.28782313662425576f);   // ln(10000)/32
    float ang = (float)s * inv;
    float c = cosf(ang), sn = sinf(ang);
    size_t base = (size_t)m * DD + hh * HDIM + i;
    float x1 = p[base];
    float x2 = p[base + 32];
    float y1 = x1 * c - x2 * sn;
    float y2 = x2 * c + x1 * sn;
    __half h1 = __float2half_rn(y1);
    __half h2 = __float2half_rn(y2);
    __half l1 = __float2half_rn(y1 - __half2float(h1));
    __half l2 = __float2half_rn(y2 - __half2float(h2));
    ohi[base] = h1; ohi[base + 32] = h2;
    olo[base] = l1; olo[base + 32] = l2;
}

// silu(gate) * up -> fp16 act
__global__ void silu_mul_kernel(const float* __restrict__ g,
                                const float* __restrict__ u,
                                __half* __restrict__ act) {
    int i = blockIdx.x * blockDim.x + threadIdx.x;
    float4 gv = ((const float4*)g)[i];
    float4 uv = ((const float4*)u)[i];
    float a0 = uv.x * gv.x / (1.f + expf(-gv.x));
    float a1 = uv.y * gv.y / (1.f + expf(-gv.y));
    float a2 = uv.z * gv.z / (1.f + expf(-gv.z));
    float a3 = uv.w * gv.w / (1.f + expf(-gv.w));
    __half2 h01 = __floats2half2_rn(a0, a1);
    __half2 h23 = __floats2half2_rn(a2, a3);
    uint2 o;
    o.x = *(uint32_t*)&h01;
    o.y = *(uint32_t*)&h23;
    ((uint2*)act)[i] = o;
}

// ---------------- fp16 tensor-core GEMM, 3-stage cp.async ------------------
// C[M,N](fp32) = A[M,K](fp16) @ W[N,K](fp16)^T (+bias, +res, opt tf32-round).
// CTA tile 128 x (NT*32), 256 threads, 8 warps (2 x 4), warp tile 64 x (NT*8).

struct GemmArgs {
    const __half* w[3];
    const float* b[3];
    float* c[3];
    int rnd[3];          // round output to tf32 (for V, feeds phase-D mma)
};

#define HS_STR 40                         // halfs per smem row (80 B, pad 8)

template<bool HAS_BIAS, bool HAS_RES, int NT>
__global__ void __launch_bounds__(256)
gemm_f16(const __half* __restrict__ A, GemmArgs args,
         const float* __restrict__ res, int M, int N, int K) {
    constexpr int BROWS  = NT * 32;           // 128 or 64
    constexpr int ASTAGE = 128 * HS_STR;
    constexpr int BSTAGE = BROWS * HS_STR;

    const __half* __restrict__ W = args.w[blockIdx.z];
    const float* __restrict__ bias = args.b[blockIdx.z];
    float* __restrict__ C = args.c[blockIdx.z];
    const bool do_rnd = args.rnd[blockIdx.z] != 0;

    extern __shared__ __half smh[];
    __half* Asb = smh;                        // 3 stages of [128][40]
    __half* Bsb = smh + 3 * ASTAGE;           // 3 stages of [BROWS][40]

    int bm = blockIdx.y, bn = blockIdx.x;
    int tid = threadIdx.x;
    int lane = tid & 31, warp = tid >> 5;
    int wm = (warp >> 2) * 64;
    int wn = (warp & 3) * (NT * 8);
    int r = lane >> 2, cq = lane & 3;

    float acc[4][NT][4];
    #pragma unroll
    for (int i = 0; i < 4; i++)
        #pragma unroll
        for (int j = 0; j < NT; j++)
            #pragma unroll
            for (int t = 0; t < 4; t++) acc[i][j][t] = 0.f;

    const __half* Abase = A + (size_t)(bm * 128) * K;
    const __half* Wbase = W + (size_t)(bn * BROWS) * K;
    int lr = tid >> 2;
    int lc = (tid & 3) * 8;

    auto load_tile = [&](int st, int k0) {
        __half* As = Asb + st * ASTAGE;
        __half* Bs = Bsb + st * BSTAGE;
        #pragma unroll
        for (int i = 0; i < 2; i++) {
            int row = lr + 64 * i;
            cp16(&As[row * HS_STR + lc], Abase + (size_t)row * K + k0 + lc);
        }
        #pragma unroll
        for (int i = 0; i < BROWS / 64; i++) {
            int row = lr + 64 * i;
            cp16(&Bs[row * HS_STR + lc], Wbase + (size_t)row * K + k0 + lc);
        }
    };

    int nk = K >> 5;
    load_tile(0, 0);
    asm volatile("cp.async.commit_group;\n" ::);
    load_tile(1, 32);
    asm volatile("cp.async.commit_group;\n" ::);

    int a_row = lane & 15, a_col = (lane >> 4) * 8;
    int b_row = lane & 7,  b_col = ((lane >> 3) & 1) * 8;

    int s = 0;
    for (int kt = 0; kt < nk; kt++) {
        if (kt + 1 < nk) {
            asm volatile("cp.async.wait_group 1;\n" ::);
        } else {
            asm volatile("cp.async.wait_group 0;\n" ::);
        }
        __syncthreads();
        if (kt + 2 < nk) {
            int s2 = s + 2; if (s2 >= 3) s2 -= 3;
            load_tile(s2, (kt + 2) * 32);
            asm volatile("cp.async.commit_group;\n" ::);
        }

        const __half* As = Asb + s * ASTAGE;
        const __half* Bs = Bsb + s * BSTAGE;
        #pragma unroll
        for (int ks = 0; ks < 2; ks++) {
            int kb = ks * 16;
            uint32_t af[4][4], bf[NT][2];
            #pragma unroll
            for (int mt = 0; mt < 4; mt++)
                ldmx4(af[mt], smem_u32(&As[(wm + mt * 16 + a_row) * HS_STR + kb + a_col]));
            #pragma unroll
            for (int nt = 0; nt < NT; nt++)
                ldmx2(bf[nt], smem_u32(&Bs[(wn + nt * 8 + b_row) * HS_STR + kb + b_col]));
            #pragma unroll
            for (int mt = 0; mt < 4; mt++)
                #pragma unroll
                for (int nt = 0; nt < NT; nt++)
                    mma16h(acc[mt][nt], af[mt], bf[nt]);
        }
        s = s + 1; if (s >= 3) s -= 3;
    }

    // epilogue (fp32 out)
    #pragma unroll
    for (int mt = 0; mt < 4; mt++) {
        int row0 = bm * 128 + wm + mt * 16 + r;
        #pragma unroll
        for (int nt = 0; nt < NT; nt++) {
            int col = bn * BROWS + wn + nt * 8 + 2 * cq;
            float2 v0 = make_float2(acc[mt][nt][0], acc[mt][nt][1]);
            float2 v1 = make_float2(acc[mt][nt][2], acc[mt][nt][3]);
            if (HAS_BIAS) {
                float2 bb = *(const float2*)(bias + col);
                v0.x += bb.x; v0.y += bb.y; v1.x += bb.x; v1.y += bb.y;
            }
            size_t i0 = (size_t)row0 * N + col;
            size_t i1 = i0 + (size_t)8 * N;
            if (HAS_RES) {
                float2 r0 = *(const float2*)(res + i0);
                float2 r1 = *(const float2*)(res + i1);
                v0.x += r0.x; v0.y += r0.y; v1.x += r1.x; v1.y += r1.y;
            }
            if (do_rnd) {
                v0.x = rnd_tf32(v0.x); v0.y = rnd_tf32(v0.y);
                v1.x = rnd_tf32(v1.x); v1.y = rnd_tf32(v1.y);
            }
            *(float2*)(C + i0) = v0;
            *(float2*)(C + i1) = v1;
        }
    }
}

#define GSMEM_NT4 ((3 * 128 * HS_STR + 3 * 128 * HS_STR) * 2)   // 61440
#define GSMEM_NT2 ((3 * 128 * HS_STR + 3 * 64  * HS_STR) * 2)   // 46080

// ---------------- sliding-window attention (512 threads) -------------------
#define KQ_STR 72                        // halfs per q/k smem row (144 B)
#define AQ_STR 68                        // floats per V smem row
#define ASC_STR 321
#define OFF_QHI 0
#define OFF_QLO 9216
#define OFF_KV  18432
#define OFF_SC  55296
#define ATTN_SMEM (55296 + 64 * ASC_STR * 4)   // 137472

__global__ void __launch_bounds__(512)
attn_kernel(const __half* __restrict__ qhi_g, const __half* __restrict__ qlo_g,
            const __half* __restrict__ khi_g, const __half* __restrict__ klo_g,
            const float* __restrict__ v, __half* __restrict__ ao,
            float* __restrict__ attn_out) {
    extern __shared__ char smraw[];
    __half* Qhi = (__half*)(smraw + OFF_QHI);
    __half* Qlo = (__half*)(smraw + OFF_QLO);
    __half* Khi[2] = { (__half*)(smraw + OFF_KV),         (__half*)(smraw + OFF_KV + 18432) };
    __half* Klo[2] = { (__half*)(smraw + OFF_KV + 9216),  (__half*)(smraw + OFF_KV + 27648) };
    float*  Vb[2]  = { (float*)(smraw + OFF_KV),          (float*)(smraw + OFF_KV + 17408) };
    float* sc = (float*)(smraw + OFF_SC);

    int q0 = blockIdx.x * 64;
    int bh = blockIdx.y;
    int b  = bh >> 4, h = bh & 15;
    int tid = threadIdx.x;
    int lane = tid & 31, warp = tid >> 5;
    int wq = (warp & 3) * 16;
    int wn = (warp >> 2) * 16;
    int r = lane >> 2, cq = lane & 3;
    int a_row = lane & 15, a_col = (lane >> 4) * 8;
    int b_row = lane & 7,  b_col = ((lane >> 3) & 1) * 8;
    const float scale = 0.125f;

    const __half* khb = khi_g + (size_t)(b * SS) * DD + h * HDIM;
    const __half* klb = klo_g + (size_t)(b * SS) * DD + h * HDIM;
    const float*  vbase = v + (size_t)(b * SS) * DD + h * HDIM;

    {
        int qq = tid >> 3, dq = (tid & 7) * 8;
        const __half* qh = qhi_g + (size_t)(b * SS + q0 + qq) * DD + h * HDIM + dq;
        const __half* ql = qlo_g + (size_t)(b * SS + q0 + qq) * DD + h * HDIM + dq;
        cp16(&Qhi[qq * KQ_STR + dq], qh);
        cp16(&Qlo[qq * KQ_STR + dq], ql);
    }

    auto loadK = [&](int buf, int jb) {
        int kk = tid >> 3, dq = (tid & 7) * 8;
        int j = jb + kk;
        if (j >= 0) {
            cp16(&Khi[buf][kk * KQ_STR + dq], khb + (size_t)j * DD + dq);
            cp16(&Klo[buf][kk * KQ_STR + dq], klb + (size_t)j * DD + dq);
        } else {
            uint4 z = make_uint4(0, 0, 0, 0);
            *(uint4*)&Khi[buf][kk * KQ_STR + dq] = z;
            *(uint4*)&Klo[buf][kk * KQ_STR + dq] = z;
        }
    };

    // -------- Phase A: scores via fp16 hi/lo 3-product mma ----------------
    loadK(0, q0 - 256);
    asm volatile("cp.async.commit_group;\n" ::);
    for (int c = 0; c < 5; c++) {
        if (c < 4) {
            loadK((c + 1) & 1, q0 - 256 + (c + 1) * 64);
            asm volatile("cp.async.commit_group;\n" ::);
            asm volatile("cp.async.wait_group 1;\n" ::);
        } else {
            asm volatile("cp.async.wait_group 0;\n" ::);
        }
        __syncthreads();
        const __half* KH = Khi[c & 1];
        const __half* KL = Klo[c & 1];

        float acc[2][4];
        #pragma unroll
        for (int i = 0; i < 2; i++)
            #pragma unroll
            for (int j = 0; j < 4; j++) acc[i][j] = 0.f;

        #pragma unroll
        for (int ks = 0; ks < 4; ks++) {
            int kb = ks * 16;
            uint32_t ahi[4], alo[4];
            ldmx4(ahi, smem_u32(&Qhi[(wq + a_row) * KQ_STR + kb + a_col]));
            ldmx4(alo, smem_u32(&Qlo[(wq + a_row) * KQ_STR + kb + a_col]));
            #pragma unroll
            for (int nt = 0; nt < 2; nt++) {
                uint32_t bhi[2], blo[2];
                ldmx2(bhi, smem_u32(&KH[(wn + nt * 8 + b_row) * KQ_STR + kb + b_col]));
                ldmx2(blo, smem_u32(&KL[(wn + nt * 8 + b_row) * KQ_STR + kb + b_col]));
                mma16h(acc[nt], ahi, bhi);
                mma16h(acc[nt], ahi, blo);
                mma16h(acc[nt], alo, bhi);
            }
        }

        int jb = q0 - 256 + c * 64;
        #pragma unroll
        for (int nt = 0; nt < 2; nt++) {
            int jl = wn + nt * 8 + 2 * cq;
            #pragma unroll
            for (int u = 0; u < 2; u++) {
                int qq = wq + r + u * 8;
                int qi = q0 + qq;
                #pragma unroll
                for (int w2 = 0; w2 < 2; w2++) {
                    int jj = jb + jl + w2;
                    bool valid = (jj >= 0) && (jj <= qi) && (qi - jj < WIN);
                    sc[qq * ASC_STR + c * 64 + jl + w2] =
                        valid ? acc[nt][u * 2 + w2] * scale : -1e30f;
                }
            }
        }
        __syncthreads();
    }

    // -------- Phase B: softmax, 8 threads per row -------------------------
    {
        int qq = tid >> 3, g = tid & 7;
        float* row = sc + qq * ASC_STR;
        float mx = -1e30f;
        for (int s = g; s < 320; s += 8) mx = fmaxf(mx, row[s]);
        mx = fmaxf(mx, __shfl_xor_sync(0xffffffffu, mx, 1));
        mx = fmaxf(mx, __shfl_xor_sync(0xffffffffu, mx, 2));
        mx = fmaxf(mx, __shfl_xor_sync(0xffffffffu, mx, 4));
        float sum = 0.f;
        for (int s = g; s < 320; s += 8) {
            float e = expf(row[s] - mx);
            row[s] = e;
            sum += e;
        }
        sum += __shfl_xor_sync(0xffffffffu, sum, 1);
        sum += __shfl_xor_sync(0xffffffffu, sum, 2);
        sum += __shfl_xor_sync(0xffffffffu, sum, 4);
        float inv = 1.f / sum;
        for (int s = g; s < 320; s += 8) row[s] *= inv;
    }
    __syncthreads();

    // -------- Phase C: write full attn rows (zeros + probs) ---------------
    {
        int c4 = tid & 255;
        int half = tid >> 8;
        for (int it = 0; it < 32; it++) {
            int qq = it * 2 + half;
            int qi = q0 + qq;
            const float* src = sc + qq * ASC_STR;
            float rr[4];
            #pragma unroll
            for (int u = 0; u < 4; u++) {
                int j = c4 * 4 + u;
                bool in = (j <= qi) && (qi - j < WIN);
                rr[u] = in ? src[j - q0 + 256] : 0.f;
            }
            ((float4*)(attn_out + ((size_t)bh * SS + qi) * SS))[c4] =
                make_float4(rr[0], rr[1], rr[2], rr[3]);
        }
    }
    __syncthreads();

    // -------- Phase D: out = P @ V (tf32), double-buffered V ---------------
    float oacc[2][4];
    #pragma unroll
    for (int i = 0; i < 2; i++)
        #pragma unroll
        for (int j = 0; j < 4; j++) oacc[i][j] = 0.f;

    auto loadV = [&](int buf, int jb) {
        #pragma unroll
        for (int i = 0; i < 2; i++) {
            int ch = tid + 512 * i;
            int kk = ch >> 4, dq = (ch & 15) * 4;
            int j = jb + kk;
            if (j >= 0) cp16(&Vb[buf][kk * AQ_STR + dq], vbase + (size_t)j * DD + dq);
            else *(float4*)&Vb[buf][kk * AQ_STR + dq] = make_float4(0.f, 0.f, 0.f, 0.f);
        }
    };

    loadV(0, q0 - 256);
    asm volatile("cp.async.commit_group;\n" ::);
    for (int c = 0; c < 5; c++) {
        if (c < 4) {
            loadV((c + 1) & 1, q0 - 256 + (c + 1) * 64);
            asm volatile("cp.async.commit_group;\n" ::);
            asm volatile("cp.async.wait_group 1;\n" ::);
        } else {
            asm volatile("cp.async.wait_group 0;\n" ::);
        }
        __syncthreads();
        const float* Vs = Vb[c & 1];   // [kk][d]

        #pragma unroll
        for (int kb = 0; kb < 64; kb += 8) {
            uint32_t ah[4];
            ah[0] = f2tf32(sc[(wq + r)     * ASC_STR + c * 64 + kb + cq]);
            ah[1] = f2tf32(sc[(wq + r + 8) * ASC_STR + c * 64 + kb + cq]);
            ah[2] = f2tf32(sc[(wq + r)     * ASC_STR + c * 64 + kb + cq + 4]);
            ah[3] = f2tf32(sc[(wq + r + 8) * ASC_STR + c * 64 + kb + cq + 4]);
            #pragma unroll
            for (int nt = 0; nt < 2; nt++) {
                uint32_t bb[2];
                bb[0] = __float_as_uint(Vs[(kb + cq)     * AQ_STR + wn + nt * 8 + r]);
                bb[1] = __float_as_uint(Vs[(kb + cq + 4) * AQ_STR + wn + nt * 8 + r]);
                mma8(oacc[nt], ah, bb);
            }
        }
        __syncthreads();
    }

    #pragma unroll
    for (int nt = 0; nt < 2; nt++) {
        int d0 = wn + nt * 8 + 2 * cq;
        size_t b0 = ((size_t)(b * SS + q0 + wq + r))     * DD + h * HDIM + d0;
        size_t b1 = ((size_t)(b * SS + q0 + wq + r + 8)) * DD + h * HDIM + d0;
        __half2 h0 = __floats2half2_rn(oacc[nt][0], oacc[nt][1]);
        __half2 h1 = __floats2half2_rn(oacc[nt][2], oacc[nt][3]);
        *(__half2*)(ao + b0) = h0;
        *(__half2*)(ao + b1) = h1;
    }
}

// ---------------- launcher -------------------------------------------------
extern "C" void kernel_launch(void* const* d_in, const int* in_sizes, int n_in,
                              void* d_out, int out_size) {
    const float* x   = (const float*)d_in[0];
    const float* wq  = (const float*)d_in[1];
    const float* bq  = (const float*)d_in[2];
    const float* wk  = (const float*)d_in[3];
    const float* bk  = (const float*)d_in[4];
    const float* wv  = (const float*)d_in[5];
    const float* bv  = (const float*)d_in[6];
    const float* wo  = (const float*)d_in[7];
    const float* bo  = (const float*)d_in[8];
    const float* anw = (const float*)d_in[9];
    const float* fnw = (const float*)d_in[10];
    const float* gw  = (const float*)d_in[11];
    const float* uw  = (const float*)d_in[12];
    const float* dw  = (const float*)d_in[13];

    float* outx = (float*)d_out;                       // [B,S,D]
    float* outa = outx + (size_t)MR * DD;              // [B,H,S,S]

    float *p_q, *p_k, *p_v, *p_x1, *p_gate, *p_up;
    __half *p_hh, *p_h2h, *p_aoh, *p_acth, *p_wh;
    __half *p_qhi, *p_qlo, *p_khi, *p_klo;
    cudaGetSymbolAddress((void**)&p_q,    g_q);
    cudaGetSymbolAddress((void**)&p_k,    g_k);
    cudaGetSymbolAddress((void**)&p_v,    g_v);
    cudaGetSymbolAddress((void**)&p_x1,   g_x1);
    cudaGetSymbolAddress((void**)&p_gate, g_gate);
    cudaGetSymbolAddress((void**)&p_up,   g_up);
    cudaGetSymbolAddress((void**)&p_hh,   g_hh);
    cudaGetSymbolAddress((void**)&p_h2h,  g_h2h);
    cudaGetSymbolAddress((void**)&p_aoh,  g_aoh);
    cudaGetSymbolAddress((void**)&p_acth, g_acth);
    cudaGetSymbolAddress((void**)&p_wh,   g_wh);
    cudaGetSymbolAddress((void**)&p_qhi,  g_qhi);
    cudaGetSymbolAddress((void**)&p_qlo,  g_qlo);
    cudaGetSymbolAddress((void**)&p_khi,  g_khi);
    cudaGetSymbolAddress((void**)&p_klo,  g_klo);

    const size_t MB1 = 1024 * 1024;
    __half* hwq = p_wh;            __half* hwk = p_wh + 1 * MB1;
    __half* hwv = p_wh + 2 * MB1;  __half* hwo = p_wh + 3 * MB1;
    __half* hgw = p_wh + 4 * MB1;  __half* huw = p_wh + 8 * MB1;
    __half* hdw = p_wh + 12 * MB1;

    cudaFuncSetAttribute(attn_kernel,
                         cudaFuncAttributeMaxDynamicSharedMemorySize, ATTN_SMEM);
    cudaFuncSetAttribute(gemm_f16<true, false, 4>,
                         cudaFuncAttributeMaxDynamicSharedMemorySize, GSMEM_NT4);
    cudaFuncSetAttribute(gemm_f16<false, false, 4>,
                         cudaFuncAttributeMaxDynamicSharedMemorySize, GSMEM_NT4);
    cudaFuncSetAttribute(gemm_f16<true, true, 2>,
                         cudaFuncAttributeMaxDynamicSharedMemorySize, GSMEM_NT2);
    cudaFuncSetAttribute(gemm_f16<false, true, 2>,
                         cudaFuncAttributeMaxDynamicSharedMemorySize, GSMEM_NT2);

    // 0) weights -> fp16 in one launch
    {
        WSet ws;
        ws.src[0] = (const float4*)wq; ws.dst[0] = hwq; ws.n4[0] = 262144;
        ws.src[1] = (const float4*)wk; ws.dst[1] = hwk; ws.n4[1] = 262144;
        ws.src[2] = (const float4*)wv; ws.dst[2] = hwv; ws.n4[2] = 262144;
        ws.src[3] = (const float4*)wo; ws.dst[3] = hwo; ws.n4[3] = 262144;
        ws.src[4] = (const float4*)gw; ws.dst[4] = hgw; ws.n4[4] = 1048576;
        ws.src[5] = (const float4*)uw; ws.dst[5] = huw; ws.n4[5] = 1048576;
        ws.src[6] = (const float4*)dw; ws.dst[6] = hdw; ws.n4[6] = 1048576;
        round_weights_kernel<<<dim3(4096, 7), 256>>>(ws);
    }

    // 1) attn rmsnorm -> fp16
    rmsnorm_kernel<<<MR, 256>>>(x, anw, p_hh);

    // 2) QKV — one z=3 fp16 launch; V tf32-rounded in epilogue
    {
        GemmArgs a = {};
        a.w[0] = hwq; a.w[1] = hwk; a.w[2] = hwv;
        a.b[0] = bq;  a.b[1] = bk;  a.b[2] = bv;
        a.c[0] = p_q; a.c[1] = p_k; a.c[2] = p_v;
        a.rnd[0] = 0; a.rnd[1] = 0; a.rnd[2] = 1;
        gemm_f16<true, false, 4><<<dim3(DD/128, MR/128, 3), 256, GSMEM_NT4>>>(
            p_hh, a, nullptr, MR, DD, DD);
    }
    // 3) RoPE -> fp16 hi/lo arrays
    rope_kernel<<<(2 * MR * 512) / 256, 256>>>(p_q, p_k, p_qhi, p_qlo, p_khi, p_klo);
    // 4) attention (probs -> outa, context -> g_aoh fp16)
    attn_kernel<<<dim3(SS / 64, BB * HH), 512, ATTN_SMEM>>>(
        p_qhi, p_qlo, p_khi, p_klo, p_v, p_aoh, outa);
    // 5) O proj + bias + residual  (NT=2: 256 CTAs -> full machine)
    {
        GemmArgs a = {};
        a.w[0] = hwo; a.b[0] = bo; a.c[0] = p_x1;
        gemm_f16<true, true, 2><<<dim3(DD/64, MR/128, 1), 256, GSMEM_NT2>>>(
            p_aoh, a, x, MR, DD, DD);
    }
    // 6) ffn rmsnorm -> fp16
    rmsnorm_kernel<<<MR, 256>>>(p_x1, fnw, p_h2h);
    // 7) gate + up in one z=2 launch
    {
        GemmArgs a = {};
        a.w[0] = hgw; a.w[1] = huw;
        a.c[0] = p_gate; a.c[1] = p_up;
        gemm_f16<false, false, 4><<<dim3(FF/128, MR/128, 2), 256, GSMEM_NT4>>>(
            p_h2h, a, nullptr, MR, FF, DD);
    }
    // 8) act = silu(gate) * up -> fp16
    silu_mul_kernel<<<(MR * FF / 4) / 256, 256>>>(p_gate, p_up, p_acth);
    // 9) down + residual -> final x  (NT=2: 256 CTAs -> full machine)
    {
        GemmArgs a = {};
        a.w[0] = hdw; a.c[0] = outx;
        gemm_f16<false, true, 2><<<dim3(DD/64, MR/128, 1), 256, GSMEM_NT2>>>(
            p_acth, a, p_x1, MR, DD, FF);
    }
}

// round 16
// speedup vs baseline: 1.0607x; 1.0123x over previous
#include <cuda_runtime.h>
#include <cuda_fp16.h>
#include <cstdint>

// Problem constants
#define BB   2
#define SS   1024
#define DD   1024
#define HH   16
#define HDIM 64
#define WIN  256
#define FF   4096
#define MR   (BB*SS)   // 2048 rows

// ---------------- scratch (device globals; no allocation allowed) ----------
__device__ float  g_q   [MR*DD];
__device__ float  g_k   [MR*DD];
__device__ float  g_v   [MR*DD];
__device__ float  g_x1  [MR*DD];
__device__ __half g_hh  [MR*DD];    // rmsnorm1 out (fp16, GEMM A)
__device__ __half g_h2h [MR*DD];    // rmsnorm2 out
__device__ __half g_aoh [MR*DD];    // attn context out
__device__ __half g_acth[MR*FF];    // silu(gate)*up
__device__ __half g_qhi [MR*DD];
__device__ __half g_qlo [MR*DD];
__device__ __half g_khi [MR*DD];
__device__ __half g_klo [MR*DD];
__device__ __half g_wh  [16*1024*1024];  // fp16 weights: wq wk wv wo gw uw dw

// ---------------- common PTX helpers ---------------------------------------
__device__ __forceinline__ void cp16(void* smem_dst, const void* gsrc) {
    uint32_t s = (uint32_t)__cvta_generic_to_shared(smem_dst);
    asm volatile("cp.async.cg.shared.global [%0], [%1], 16;\n" :: "r"(s), "l"(gsrc));
}
__device__ __forceinline__ uint32_t f2tf32(float x) {
    uint32_t u;
    asm("cvt.rna.tf32.f32 %0, %1;" : "=r"(u) : "f"(x));
    return u;
}
__device__ __forceinline__ float rnd_tf32(float x) {
    return __uint_as_float(f2tf32(x));
}
__device__ __forceinline__ void mma8(float* d, const uint32_t* a, const uint32_t* b) {
    asm volatile(
        "mma.sync.aligned.m16n8k8.row.col.f32.tf32.tf32.f32 "
        "{%0,%1,%2,%3}, {%4,%5,%6,%7}, {%8,%9}, {%0,%1,%2,%3};\n"
        : "+f"(d[0]), "+f"(d[1]), "+f"(d[2]), "+f"(d[3])
        : "r"(a[0]), "r"(a[1]), "r"(a[2]), "r"(a[3]), "r"(b[0]), "r"(b[1]));
}
__device__ __forceinline__ void mma16h(float* d, const uint32_t* a, const uint32_t* b) {
    asm volatile(
        "mma.sync.aligned.m16n8k16.row.col.f32.f16.f16.f32 "
        "{%0,%1,%2,%3}, {%4,%5,%6,%7}, {%8,%9}, {%0,%1,%2,%3};\n"
        : "+f"(d[0]), "+f"(d[1]), "+f"(d[2]), "+f"(d[3])
        : "r"(a[0]), "r"(a[1]), "r"(a[2]), "r"(a[3]), "r"(b[0]), "r"(b[1]));
}
__device__ __forceinline__ void ldmx4(uint32_t* r, uint32_t addr) {
    asm volatile("ldmatrix.sync.aligned.m8n8.x4.shared.b16 {%0,%1,%2,%3}, [%4];"
                 : "=r"(r[0]), "=r"(r[1]), "=r"(r[2]), "=r"(r[3]) : "r"(addr));
}
__device__ __forceinline__ void ldmx2(uint32_t* r, uint32_t addr) {
    asm volatile("ldmatrix.sync.aligned.m8n8.x2.shared.b16 {%0,%1}, [%2];"
                 : "=r"(r[0]), "=r"(r[1]) : "r"(addr));
}
__device__ __forceinline__ uint32_t smem_u32(const void* p) {
    return (uint32_t)__cvta_generic_to_shared(p);
}

// ---------------- elementwise kernels ---------------------------------------
struct WSet {
    const float4* src[7];
    __half* dst[7];
    int n4[7];
};

__global__ void round_weights_kernel(WSet ws) {
    int reg = blockIdx.y;
    int i = blockIdx.x * 256 + threadIdx.x;
    if (i < ws.n4[reg]) {
        float4 v = ws.src[reg][i];
        __half2 h01 = __floats2half2_rn(v.x, v.y);
        __half2 h23 = __floats2half2_rn(v.z, v.w);
        uint2 o;
        o.x = *(uint32_t*)&h01;
        o.y = *(uint32_t*)&h23;
        ((uint2*)ws.dst[reg])[i] = o;
    }
}

// RMSNorm: fp32 in, fp16 out (feeds GEMM A side)
__global__ void rmsnorm_kernel(const float* __restrict__ x,
                               const float* __restrict__ w,
                               __half* __restrict__ out) {
    int row = blockIdx.x;
    int tid = threadIdx.x;
    const float4 xv = ((const float4*)(x + (size_t)row * DD))[tid];
    float ss = xv.x*xv.x + xv.y*xv.y + xv.z*xv.z + xv.w*xv.w;
    #pragma unroll
    for (int o = 16; o; o >>= 1) ss += __shfl_xor_sync(0xffffffffu, ss, o);
    __shared__ float red[8];
    if ((tid & 31) == 0) red[tid >> 5] = ss;
    __syncthreads();
    if (tid < 32) {
        float v = (tid < 8) ? red[tid] : 0.f;
        #pragma unroll
        for (int o = 4; o; o >>= 1) v += __shfl_xor_sync(0xffffffffu, v, o);
        if (tid == 0) red[0] = v;
    }
    __syncthreads();
    float inv = rsqrtf(red[0] * (1.0f / DD) + 1e-6f);
    float4 wv = ((const float4*)w)[tid];
    __half2 h01 = __floats2half2_rn(xv.x * inv * wv.x, xv.y * inv * wv.y);
    __half2 h23 = __floats2half2_rn(xv.z * inv * wv.z, xv.w * inv * wv.w);
    uint2 o;
    o.x = *(uint32_t*)&h01;
    o.y = *(uint32_t*)&h23;
    ((uint2*)(out + (size_t)row * DD))[tid] = o;
}

// RoPE: reads fp32 q/k, writes rotated values as fp16 hi/lo pairs
__global__ void rope_kernel(const float* __restrict__ q, const float* __restrict__ k,
                            __half* __restrict__ qhi, __half* __restrict__ qlo,
                            __half* __restrict__ khi, __half* __restrict__ klo) {
    int t = blockIdx.x * blockDim.x + threadIdx.x;
    int total = MR * 512;
    const float* p = (t < total) ? q : k;
    __half* ohi = (t < total) ? qhi : khi;
    __half* olo = (t < total) ? qlo : klo;
    int u = (t < total) ? t : (t - total);
    int m  = u >> 9;
    int pr = u & 511;
    int hh = pr >> 5;
    int i  = pr & 31;
    int s  = m & (SS - 1);
    float inv = expf(-(float)i * 0.28782313662425576f);   // ln(10000)/32
    float ang = (float)s * inv;
    float c = cosf(ang), sn = sinf(ang);
    size_t base = (size_t)m * DD + hh * HDIM + i;
    float x1 = p[base];
    float x2 = p[base + 32];
    float y1 = x1 * c - x2 * sn;
    float y2 = x2 * c + x1 * sn;
    __half h1 = __float2half_rn(y1);
    __half h2 = __float2half_rn(y2);
    __half l1 = __float2half_rn(y1 - __half2float(h1));
    __half l2 = __float2half_rn(y2 - __half2float(h2));
    ohi[base] = h1; ohi[base + 32] = h2;
    olo[base] = l1; olo[base + 32] = l2;
}

// ---------------- fp16 tensor-core GEMM, 3-stage cp.async ------------------
// C[M,N](fp32) = A[M,K](fp16) @ W[N,K](fp16)^T (+bias, +res, opt tf32-round).
// 128x128x32 tile, 256 threads, 8 warps (2x4), warp tile 64x32.

struct GemmArgs {
    const __half* w[3];
    const float* b[3];
    float* c[3];
    int rnd[3];          // round output to tf32 (for V, feeds phase-D mma)
};

#define HS_STR 40                         // halfs per smem row (80 B, pad 8)
#define HS_TILE (128 * HS_STR)            // halfs per stage per matrix
#define GEMM_SMEM (6 * HS_TILE * 2)       // 3 stages x (A+B) bytes = 61440

template<bool HAS_BIAS, bool HAS_RES>
__global__ void __launch_bounds__(256)
gemm_f16(const __half* __restrict__ A, GemmArgs args,
         const float* __restrict__ res, int M, int N, int K) {
    const __half* __restrict__ W = args.w[blockIdx.z];
    const float* __restrict__ bias = args.b[blockIdx.z];
    float* __restrict__ C = args.c[blockIdx.z];
    const bool do_rnd = args.rnd[blockIdx.z] != 0;

    extern __shared__ __half smh[];
    __half* Asb = smh;                    // 3 stages of [128][40]
    __half* Bsb = smh + 3 * HS_TILE;

    int bm = blockIdx.y, bn = blockIdx.x;
    int tid = threadIdx.x;
    int lane = tid & 31, warp = tid >> 5;
    int wm = (warp >> 2) * 64;
    int wn = (warp & 3) * 32;
    int r = lane >> 2, cq = lane & 3;

    float acc[4][4][4];
    #pragma unroll
    for (int i = 0; i < 4; i++)
        #pragma unroll
        for (int j = 0; j < 4; j++)
            #pragma unroll
            for (int t = 0; t < 4; t++) acc[i][j][t] = 0.f;

    const __half* Abase = A + (size_t)(bm * 128) * K;
    const __half* Wbase = W + (size_t)(bn * 128) * K;
    int lr = tid >> 2;
    int lc = (tid & 3) * 8;

    auto load_tile = [&](int st, int k0) {
        __half* As = Asb + st * HS_TILE;
        __half* Bs = Bsb + st * HS_TILE;
        #pragma unroll
        for (int i = 0; i < 2; i++) {
            int row = lr + 64 * i;
            cp16(&As[row * HS_STR + lc], Abase + (size_t)row * K + k0 + lc);
            cp16(&Bs[row * HS_STR + lc], Wbase + (size_t)row * K + k0 + lc);
        }
    };

    int nk = K >> 5;
    load_tile(0, 0);
    asm volatile("cp.async.commit_group;\n" ::);
    load_tile(1, 32);
    asm volatile("cp.async.commit_group;\n" ::);

    int a_row = lane & 15, a_col = (lane >> 4) * 8;
    int b_row = lane & 7,  b_col = ((lane >> 3) & 1) * 8;

    int s = 0;
    for (int kt = 0; kt < nk; kt++) {
        if (kt + 1 < nk) {
            asm volatile("cp.async.wait_group 1;\n" ::);
        } else {
            asm volatile("cp.async.wait_group 0;\n" ::);
        }
        __syncthreads();
        if (kt + 2 < nk) {
            int s2 = s + 2; if (s2 >= 3) s2 -= 3;
            load_tile(s2, (kt + 2) * 32);
            asm volatile("cp.async.commit_group;\n" ::);
        }

        const __half* As = Asb + s * HS_TILE;
        const __half* Bs = Bsb + s * HS_TILE;
        #pragma unroll
        for (int ks = 0; ks < 2; ks++) {
            int kb = ks * 16;
            uint32_t af[4][4], bf[4][2];
            #pragma unroll
            for (int mt = 0; mt < 4; mt++)
                ldmx4(af[mt], smem_u32(&As[(wm + mt * 16 + a_row) * HS_STR + kb + a_col]));
            #pragma unroll
            for (int nt = 0; nt < 4; nt++)
                ldmx2(bf[nt], smem_u32(&Bs[(wn + nt * 8 + b_row) * HS_STR + kb + b_col]));
            #pragma unroll
            for (int mt = 0; mt < 4; mt++)
                #pragma unroll
                for (int nt = 0; nt < 4; nt++)
                    mma16h(acc[mt][nt], af[mt], bf[nt]);
        }
        s = s + 1; if (s >= 3) s -= 3;
    }

    // epilogue (fp32 out)
    #pragma unroll
    for (int mt = 0; mt < 4; mt++) {
        int row0 = bm * 128 + wm + mt * 16 + r;
        #pragma unroll
        for (int nt = 0; nt < 4; nt++) {
            int col = bn * 128 + wn + nt * 8 + 2 * cq;
            float2 v0 = make_float2(acc[mt][nt][0], acc[mt][nt][1]);
            float2 v1 = make_float2(acc[mt][nt][2], acc[mt][nt][3]);
            if (HAS_BIAS) {
                float2 bb = *(const float2*)(bias + col);
                v0.x += bb.x; v0.y += bb.y; v1.x += bb.x; v1.y += bb.y;
            }
            size_t i0 = (size_t)row0 * N + col;
            size_t i1 = i0 + (size_t)8 * N;
            if (HAS_RES) {
                float2 r0 = *(const float2*)(res + i0);
                float2 r1 = *(const float2*)(res + i1);
                v0.x += r0.x; v0.y += r0.y; v1.x += r1.x; v1.y += r1.y;
            }
            if (do_rnd) {
                v0.x = rnd_tf32(v0.x); v0.y = rnd_tf32(v0.y);
                v1.x = rnd_tf32(v1.x); v1.y = rnd_tf32(v1.y);
            }
            *(float2*)(C + i0) = v0;
            *(float2*)(C + i1) = v1;
        }
    }
}

// ---------------- fused gate/up/silu dual-pass GEMM ------------------------
// Pass 1: acc = A @ Wg^T; stage = fp16(silu(acc)).
// Pass 2: acc = A @ Wu^T; act = fp16(stage * acc).
#define STAGE_STR 130
#define GU_SMEM (GEMM_SMEM + 128 * STAGE_STR * 2)   // 61440 + 33280 = 94720

__global__ void __launch_bounds__(256)
gemm_gateup(const __half* __restrict__ A, const __half* __restrict__ Wg,
            const __half* __restrict__ Wu, __half* __restrict__ act,
            int M, int N, int K) {
    extern __shared__ __half smh[];
    __half* Asb = smh;
    __half* Bsb = smh + 3 * HS_TILE;
    __half* stage = smh + 6 * HS_TILE;    // [128][130] fp16

    int bm = blockIdx.y, bn = blockIdx.x;
    int tid = threadIdx.x;
    int lane = tid & 31, warp = tid >> 5;
    int wm = (warp >> 2) * 64;
    int wn = (warp & 3) * 32;
    int r = lane >> 2, cq = lane & 3;

    const __half* Abase = A + (size_t)(bm * 128) * K;
    int lr = tid >> 2;
    int lc = (tid & 3) * 8;
    int a_row = lane & 15, a_col = (lane >> 4) * 8;
    int b_row = lane & 7,  b_col = ((lane >> 3) & 1) * 8;
    int nk = K >> 5;

    float acc[4][4][4];

    #pragma unroll 1
    for (int pass = 0; pass < 2; pass++) {
        const __half* Wbase = (pass == 0 ? Wg : Wu) + (size_t)(bn * 128) * K;

        #pragma unroll
        for (int i = 0; i < 4; i++)
            #pragma unroll
            for (int j = 0; j < 4; j++)
                #pragma unroll
                for (int t = 0; t < 4; t++) acc[i][j][t] = 0.f;

        auto load_tile = [&](int st, int k0) {
            __half* As = Asb + st * HS_TILE;
            __half* Bs = Bsb + st * HS_TILE;
            #pragma unroll
            for (int i = 0; i < 2; i++) {
                int row = lr + 64 * i;
                cp16(&As[row * HS_STR + lc], Abase + (size_t)row * K + k0 + lc);
                cp16(&Bs[row * HS_STR + lc], Wbase + (size_t)row * K + k0 + lc);
            }
        };

        load_tile(0, 0);
        asm volatile("cp.async.commit_group;\n" ::);
        load_tile(1, 32);
        asm volatile("cp.async.commit_group;\n" ::);

        int s = 0;
        for (int kt = 0; kt < nk; kt++) {
            if (kt + 1 < nk) {
                asm volatile("cp.async.wait_group 1;\n" ::);
            } else {
                asm volatile("cp.async.wait_group 0;\n" ::);
            }
            __syncthreads();
            if (kt + 2 < nk) {
                int s2 = s + 2; if (s2 >= 3) s2 -= 3;
                load_tile(s2, (kt + 2) * 32);
                asm volatile("cp.async.commit_group;\n" ::);
            }

            const __half* As = Asb + s * HS_TILE;
            const __half* Bs = Bsb + s * HS_TILE;
            #pragma unroll
            for (int ks = 0; ks < 2; ks++) {
                int kb = ks * 16;
                uint32_t af[4][4], bf[4][2];
                #pragma unroll
                for (int mt = 0; mt < 4; mt++)
                    ldmx4(af[mt], smem_u32(&As[(wm + mt * 16 + a_row) * HS_STR + kb + a_col]));
                #pragma unroll
                for (int nt = 0; nt < 4; nt++)
                    ldmx2(bf[nt], smem_u32(&Bs[(wn + nt * 8 + b_row) * HS_STR + kb + b_col]));
                #pragma unroll
                for (int mt = 0; mt < 4; mt++)
                    #pragma unroll
                    for (int nt = 0; nt < 4; nt++)
                        mma16h(acc[mt][nt], af[mt], bf[nt]);
            }
            s = s + 1; if (s >= 3) s -= 3;
        }

        if (pass == 0) {
            // stage silu(gate) as fp16 (thread-private positions)
            #pragma unroll
            for (int mt = 0; mt < 4; mt++) {
                int row0 = wm + mt * 16 + r;
                #pragma unroll
                for (int nt = 0; nt < 4; nt++) {
                    int col = wn + nt * 8 + 2 * cq;
                    float s0 = acc[mt][nt][0], s1 = acc[mt][nt][1];
                    float s2 = acc[mt][nt][2], s3 = acc[mt][nt][3];
                    s0 *= 1.f / (1.f + expf(-s0));
                    s1 *= 1.f / (1.f + expf(-s1));
                    s2 *= 1.f / (1.f + expf(-s2));
                    s3 *= 1.f / (1.f + expf(-s3));
                    *(__half2*)(stage + row0 * STAGE_STR + col) =
                        __floats2half2_rn(s0, s1);
                    *(__half2*)(stage + (row0 + 8) * STAGE_STR + col) =
                        __floats2half2_rn(s2, s3);
                }
            }
            __syncthreads();   // pipeline smem safe to reuse for pass 2
        }
    }

    // epilogue: act = fp16(stage * up_acc)
    #pragma unroll
    for (int mt = 0; mt < 4; mt++) {
        int row0 = wm + mt * 16 + r;
        int grow = bm * 128 + row0;
        #pragma unroll
        for (int nt = 0; nt < 4; nt++) {
            int col = wn + nt * 8 + 2 * cq;
            float2 g0 = __half22float2(*(__half2*)(stage + row0 * STAGE_STR + col));
            float2 g1 = __half22float2(*(__half2*)(stage + (row0 + 8) * STAGE_STR + col));
            size_t i0 = (size_t)grow * N + bn * 128 + col;
            size_t i1 = i0 + (size_t)8 * N;
            *(__half2*)(act + i0) =
                __floats2half2_rn(acc[mt][nt][0] * g0.x, acc[mt][nt][1] * g0.y);
            *(__half2*)(act + i1) =
                __floats2half2_rn(acc[mt][nt][2] * g1.x, acc[mt][nt][3] * g1.y);
        }
    }
}

// ---------------- sliding-window attention (512 threads) -------------------
#define KQ_STR 72                        // halfs per q/k smem row (144 B)
#define AQ_STR 68                        // floats per V smem row
#define ASC_STR 321
#define OFF_QHI 0
#define OFF_QLO 9216
#define OFF_KV  18432
#define OFF_SC  55296
#define ATTN_SMEM (55296 + 64 * ASC_STR * 4)   // 137472

__global__ void __launch_bounds__(512)
attn_kernel(const __half* __restrict__ qhi_g, const __half* __restrict__ qlo_g,
            const __half* __restrict__ khi_g, const __half* __restrict__ klo_g,
            const float* __restrict__ v, __half* __restrict__ ao,
            float* __restrict__ attn_out) {
    extern __shared__ char smraw[];
    __half* Qhi = (__half*)(smraw + OFF_QHI);
    __half* Qlo = (__half*)(smraw + OFF_QLO);
    __half* Khi[2] = { (__half*)(smraw + OFF_KV),         (__half*)(smraw + OFF_KV + 18432) };
    __half* Klo[2] = { (__half*)(smraw + OFF_KV + 9216),  (__half*)(smraw + OFF_KV + 27648) };
    float*  Vb[2]  = { (float*)(smraw + OFF_KV),          (float*)(smraw + OFF_KV + 17408) };
    float* sc = (float*)(smraw + OFF_SC);

    int q0 = blockIdx.x * 64;
    int bh = blockIdx.y;
    int b  = bh >> 4, h = bh & 15;
    int tid = threadIdx.x;
    int lane = tid & 31, warp = tid >> 5;
    int wq = (warp & 3) * 16;
    int wn = (warp >> 2) * 16;
    int r = lane >> 2, cq = lane & 3;
    int a_row = lane & 15, a_col = (lane >> 4) * 8;
    int b_row = lane & 7,  b_col = ((lane >> 3) & 1) * 8;
    const float scale = 0.125f;

    const __half* khb = khi_g + (size_t)(b * SS) * DD + h * HDIM;
    const __half* klb = klo_g + (size_t)(b * SS) * DD + h * HDIM;
    const float*  vbase = v + (size_t)(b * SS) * DD + h * HDIM;

    {
        int qq = tid >> 3, dq = (tid & 7) * 8;
        const __half* qh = qhi_g + (size_t)(b * SS + q0 + qq) * DD + h * HDIM + dq;
        const __half* ql = qlo_g + (size_t)(b * SS + q0 + qq) * DD + h * HDIM + dq;
        cp16(&Qhi[qq * KQ_STR + dq], qh);
        cp16(&Qlo[qq * KQ_STR + dq], ql);
    }

    auto loadK = [&](int buf, int jb) {
        int kk = tid >> 3, dq = (tid & 7) * 8;
        int j = jb + kk;
        if (j >= 0) {
            cp16(&Khi[buf][kk * KQ_STR + dq], khb + (size_t)j * DD + dq);
            cp16(&Klo[buf][kk * KQ_STR + dq], klb + (size_t)j * DD + dq);
        } else {
            uint4 z = make_uint4(0, 0, 0, 0);
            *(uint4*)&Khi[buf][kk * KQ_STR + dq] = z;
            *(uint4*)&Klo[buf][kk * KQ_STR + dq] = z;
        }
    };

    // -------- Phase A: scores via fp16 hi/lo 3-product mma ----------------
    loadK(0, q0 - 256);
    asm volatile("cp.async.commit_group;\n" ::);
    for (int c = 0; c < 5; c++) {
        if (c < 4) {
            loadK((c + 1) & 1, q0 - 256 + (c + 1) * 64);
            asm volatile("cp.async.commit_group;\n" ::);
            asm volatile("cp.async.wait_group 1;\n" ::);
        } else {
            asm volatile("cp.async.wait_group 0;\n" ::);
        }
        __syncthreads();
        const __half* KH = Khi[c & 1];
        const __half* KL = Klo[c & 1];

        float acc[2][4];
        #pragma unroll
        for (int i = 0; i < 2; i++)
            #pragma unroll
            for (int j = 0; j < 4; j++) acc[i][j] = 0.f;

        #pragma unroll
        for (int ks = 0; ks < 4; ks++) {
            int kb = ks * 16;
            uint32_t ahi[4], alo[4];
            ldmx4(ahi, smem_u32(&Qhi[(wq + a_row) * KQ_STR + kb + a_col]));
            ldmx4(alo, smem_u32(&Qlo[(wq + a_row) * KQ_STR + kb + a_col]));
            #pragma unroll
            for (int nt = 0; nt < 2; nt++) {
                uint32_t bhi[2], blo[2];
                ldmx2(bhi, smem_u32(&KH[(wn + nt * 8 + b_row) * KQ_STR + kb + b_col]));
                ldmx2(blo, smem_u32(&KL[(wn + nt * 8 + b_row) * KQ_STR + kb + b_col]));
                mma16h(acc[nt], ahi, bhi);
                mma16h(acc[nt], ahi, blo);
                mma16h(acc[nt], alo, bhi);
            }
        }

        int jb = q0 - 256 + c * 64;
        #pragma unroll
        for (int nt = 0; nt < 2; nt++) {
            int jl = wn + nt * 8 + 2 * cq;
            #pragma unroll
            for (int u = 0; u < 2; u++) {
                int qq = wq + r + u * 8;
                int qi = q0 + qq;
                #pragma unroll
                for (int w2 = 0; w2 < 2; w2++) {
                    int jj = jb + jl + w2;
                    bool valid = (jj >= 0) && (jj <= qi) && (qi - jj < WIN);
                    sc[qq * ASC_STR + c * 64 + jl + w2] =
                        valid ? acc[nt][u * 2 + w2] * scale : -1e30f;
                }
            }
        }
        __syncthreads();
    }

    // -------- Phase B: softmax, 8 threads per row -------------------------
    {
        int qq = tid >> 3, g = tid & 7;
        float* row = sc + qq * ASC_STR;
        float mx = -1e30f;
        for (int s = g; s < 320; s += 8) mx = fmaxf(mx, row[s]);
        mx = fmaxf(mx, __shfl_xor_sync(0xffffffffu, mx, 1));
        mx = fmaxf(mx, __shfl_xor_sync(0xffffffffu, mx, 2));
        mx = fmaxf(mx, __shfl_xor_sync(0xffffffffu, mx, 4));
        float sum = 0.f;
        for (int s = g; s < 320; s += 8) {
            float e = expf(row[s] - mx);
            row[s] = e;
            sum += e;
        }
        sum += __shfl_xor_sync(0xffffffffu, sum, 1);
        sum += __shfl_xor_sync(0xffffffffu, sum, 2);
        sum += __shfl_xor_sync(0xffffffffu, sum, 4);
        float inv = 1.f / sum;
        for (int s = g; s < 320; s += 8) row[s] *= inv;
    }
    __syncthreads();

    // -------- Phase C: write full attn rows (zeros + probs) ---------------
    {
        int c4 = tid & 255;
        int half = tid >> 8;
        for (int it = 0; it < 32; it++) {
            int qq = it * 2 + half;
            int qi = q0 + qq;
            const float* src = sc + qq * ASC_STR;
            float rr[4];
            #pragma unroll
            for (int u = 0; u < 4; u++) {
                int j = c4 * 4 + u;
                bool in = (j <= qi) && (qi - j < WIN);
                rr[u] = in ? src[j - q0 + 256] : 0.f;
            }
            ((float4*)(attn_out + ((size_t)bh * SS + qi) * SS))[c4] =
                make_float4(rr[0], rr[1], rr[2], rr[3]);
        }
    }
    __syncthreads();

    // -------- Phase D: out = P @ V (tf32), double-buffered V ---------------
    float oacc[2][4];
    #pragma unroll
    for (int i = 0; i < 2; i++)
        #pragma unroll
        for (int j = 0; j < 4; j++) oacc[i][j] = 0.f;

    auto loadV = [&](int buf, int jb) {
        #pragma unroll
        for (int i = 0; i < 2; i++) {
            int ch = tid + 512 * i;
            int kk = ch >> 4, dq = (ch & 15) * 4;
            int j = jb + kk;
            if (j >= 0) cp16(&Vb[buf][kk * AQ_STR + dq], vbase + (size_t)j * DD + dq);
            else *(float4*)&Vb[buf][kk * AQ_STR + dq] = make_float4(0.f, 0.f, 0.f, 0.f);
        }
    };

    loadV(0, q0 - 256);
    asm volatile("cp.async.commit_group;\n" ::);
    for (int c = 0; c < 5; c++) {
        if (c < 4) {
            loadV((c + 1) & 1, q0 - 256 + (c + 1) * 64);
            asm volatile("cp.async.commit_group;\n" ::);
            asm volatile("cp.async.wait_group 1;\n" ::);
        } else {
            asm volatile("cp.async.wait_group 0;\n" ::);
        }
        __syncthreads();
        const float* Vs = Vb[c & 1];   // [kk][d]

        #pragma unroll
        for (int kb = 0; kb < 64; kb += 8) {
            uint32_t ah[4];
            ah[0] = f2tf32(sc[(wq + r)     * ASC_STR + c * 64 + kb + cq]);
            ah[1] = f2tf32(sc[(wq + r + 8) * ASC_STR + c * 64 + kb + cq]);
            ah[2] = f2tf32(sc[(wq + r)     * ASC_STR + c * 64 + kb + cq + 4]);
            ah[3] = f2tf32(sc[(wq + r + 8) * ASC_STR + c * 64 + kb + cq + 4]);
            #pragma unroll
            for (int nt = 0; nt < 2; nt++) {
                uint32_t bb[2];
                bb[0] = __float_as_uint(Vs[(kb + cq)     * AQ_STR + wn + nt * 8 + r]);
                bb[1] = __float_as_uint(Vs[(kb + cq + 4) * AQ_STR + wn + nt * 8 + r]);
                mma8(oacc[nt], ah, bb);
            }
        }
        __syncthreads();
    }

    #pragma unroll
    for (int nt = 0; nt < 2; nt++) {
        int d0 = wn + nt * 8 + 2 * cq;
        size_t b0 = ((size_t)(b * SS + q0 + wq + r))     * DD + h * HDIM + d0;
        size_t b1 = ((size_t)(b * SS + q0 + wq + r + 8)) * DD + h * HDIM + d0;
        __half2 h0 = __floats2half2_rn(oacc[nt][0], oacc[nt][1]);
        __half2 h1 = __floats2half2_rn(oacc[nt][2], oacc[nt][3]);
        *(__half2*)(ao + b0) = h0;
        *(__half2*)(ao + b1) = h1;
    }
}

// ---------------- launcher -------------------------------------------------
extern "C" void kernel_launch(void* const* d_in, const int* in_sizes, int n_in,
                              void* d_out, int out_size) {
    const float* x   = (const float*)d_in[0];
    const float* wq  = (const float*)d_in[1];
    const float* bq  = (const float*)d_in[2];
    const float* wk  = (const float*)d_in[3];
    const float* bk  = (const float*)d_in[4];
    const float* wv  = (const float*)d_in[5];
    const float* bv  = (const float*)d_in[6];
    const float* wo  = (const float*)d_in[7];
    const float* bo  = (const float*)d_in[8];
    const float* anw = (const float*)d_in[9];
    const float* fnw = (const float*)d_in[10];
    const float* gw  = (const float*)d_in[11];
    const float* uw  = (const float*)d_in[12];
    const float* dw  = (const float*)d_in[13];

    float* outx = (float*)d_out;                       // [B,S,D]
    float* outa = outx + (size_t)MR * DD;              // [B,H,S,S]

    float *p_q, *p_k, *p_v, *p_x1;
    __half *p_hh, *p_h2h, *p_aoh, *p_acth, *p_wh;
    __half *p_qhi, *p_qlo, *p_khi, *p_klo;
    cudaGetSymbolAddress((void**)&p_q,    g_q);
    cudaGetSymbolAddress((void**)&p_k,    g_k);
    cudaGetSymbolAddress((void**)&p_v,    g_v);
    cudaGetSymbolAddress((void**)&p_x1,   g_x1);
    cudaGetSymbolAddress((void**)&p_hh,   g_hh);
    cudaGetSymbolAddress((void**)&p_h2h,  g_h2h);
    cudaGetSymbolAddress((void**)&p_aoh,  g_aoh);
    cudaGetSymbolAddress((void**)&p_acth, g_acth);
    cudaGetSymbolAddress((void**)&p_wh,   g_wh);
    cudaGetSymbolAddress((void**)&p_qhi,  g_qhi);
    cudaGetSymbolAddress((void**)&p_qlo,  g_qlo);
    cudaGetSymbolAddress((void**)&p_khi,  g_khi);
    cudaGetSymbolAddress((void**)&p_klo,  g_klo);

    const size_t MB1 = 1024 * 1024;
    __half* hwq = p_wh;            __half* hwk = p_wh + 1 * MB1;
    __half* hwv = p_wh + 2 * MB1;  __half* hwo = p_wh + 3 * MB1;
    __half* hgw = p_wh + 4 * MB1;  __half* huw = p_wh + 8 * MB1;
    __half* hdw = p_wh + 12 * MB1;

    cudaFuncSetAttribute(attn_kernel,
                         cudaFuncAttributeMaxDynamicSharedMemorySize, ATTN_SMEM);
    cudaFuncSetAttribute(gemm_f16<true, false>,
                         cudaFuncAttributeMaxDynamicSharedMemorySize, GEMM_SMEM);
    cudaFuncSetAttribute(gemm_f16<true, true>,
                         cudaFuncAttributeMaxDynamicSharedMemorySize, GEMM_SMEM);
    cudaFuncSetAttribute(gemm_f16<false, true>,
                         cudaFuncAttributeMaxDynamicSharedMemorySize, GEMM_SMEM);
    cudaFuncSetAttribute(gemm_gateup,
                         cudaFuncAttributeMaxDynamicSharedMemorySize, GU_SMEM);

    // 0) weights -> fp16 in one launch
    {
        WSet ws;
        ws.src[0] = (const float4*)wq; ws.dst[0] = hwq; ws.n4[0] = 262144;
        ws.src[1] = (const float4*)wk; ws.dst[1] = hwk; ws.n4[1] = 262144;
        ws.src[2] = (const float4*)wv; ws.dst[2] = hwv; ws.n4[2] = 262144;
        ws.src[3] = (const float4*)wo; ws.dst[3] = hwo; ws.n4[3] = 262144;
        ws.src[4] = (const float4*)gw; ws.dst[4] = hgw; ws.n4[4] = 1048576;
        ws.src[5] = (const float4*)uw; ws.dst[5] = huw; ws.n4[5] = 1048576;
        ws.src[6] = (const float4*)dw; ws.dst[6] = hdw; ws.n4[6] = 1048576;
        round_weights_kernel<<<dim3(4096, 7), 256>>>(ws);
    }

    // 1) attn rmsnorm -> fp16
    rmsnorm_kernel<<<MR, 256>>>(x, anw, p_hh);

    // 2) QKV — one z=3 fp16 launch; V tf32-rounded in epilogue
    {
        GemmArgs a = {};
        a.w[0] = hwq; a.w[1] = hwk; a.w[2] = hwv;
        a.b[0] = bq;  a.b[1] = bk;  a.b[2] = bv;
        a.c[0] = p_q; a.c[1] = p_k; a.c[2] = p_v;
        a.rnd[0] = 0; a.rnd[1] = 0; a.rnd[2] = 1;
        gemm_f16<true, false><<<dim3(DD/128, MR/128, 3), 256, GEMM_SMEM>>>(
            p_hh, a, nullptr, MR, DD, DD);
    }
    // 3) RoPE -> fp16 hi/lo arrays
    rope_kernel<<<(2 * MR * 512) / 256, 256>>>(p_q, p_k, p_qhi, p_qlo, p_khi, p_klo);
    // 4) attention (probs -> outa, context -> g_aoh fp16)
    attn_kernel<<<dim3(SS / 64, BB * HH), 512, ATTN_SMEM>>>(
        p_qhi, p_qlo, p_khi, p_klo, p_v, p_aoh, outa);
    // 5) O proj + bias + residual
    {
        GemmArgs a = {};
        a.w[0] = hwo; a.b[0] = bo; a.c[0] = p_x1;
        gemm_f16<true, true><<<dim3(DD/128, MR/128, 1), 256, GEMM_SMEM>>>(
            p_aoh, a, x, MR, DD, DD);
    }
    // 6) ffn rmsnorm -> fp16
    rmsnorm_kernel<<<MR, 256>>>(p_x1, fnw, p_h2h);
    // 7) fused gate/up/silu -> fp16 act
    gemm_gateup<<<dim3(FF/128, MR/128), 256, GU_SMEM>>>(
        p_h2h, hgw, huw, p_acth, MR, FF, DD);
    // 8) down + residual -> final x
    {
        GemmArgs a = {};
        a.w[0] = hdw; a.c[0] = outx;
        gemm_f16<false, true><<<dim3(DD/128, MR/128, 1), 256, GEMM_SMEM>>>(
            p_acth, a, p_x1, MR, DD, FF);
    }
}

// round 17
// speedup vs baseline: 1.1083x; 1.0449x over previous
#include <cuda_runtime.h>
#include <cuda_fp16.h>
#include <cstdint>

// Problem constants
#define BB   2
#define SS   1024
#define DD   1024
#define HH   16
#define HDIM 64
#define WIN  256
#define FF   4096
#define MR   (BB*SS)   // 2048 rows

// ---------------- scratch (device globals; no allocation allowed) ----------
__device__ float  g_q   [MR*DD];
__device__ float  g_k   [MR*DD];
__device__ float  g_v   [MR*DD];
__device__ float  g_x1  [MR*DD];
__device__ float  g_gate[MR*FF];
__device__ float  g_up  [MR*FF];
__device__ __half g_hh  [MR*DD];    // rmsnorm1 out (fp16, GEMM A)
__device__ __half g_h2h [MR*DD];    // rmsnorm2 out
__device__ __half g_aoh [MR*DD];    // attn context out
__device__ __half g_acth[MR*FF];    // silu(gate)*up
__device__ __half g_qhi [MR*DD];
__device__ __half g_qlo [MR*DD];
__device__ __half g_khi [MR*DD];
__device__ __half g_klo [MR*DD];
__device__ __half g_wh  [16*1024*1024];  // fp16 weights: wq wk wv wo gw uw dw

// ---------------- common PTX helpers ---------------------------------------
__device__ __forceinline__ void cp16(void* smem_dst, const void* gsrc) {
    uint32_t s = (uint32_t)__cvta_generic_to_shared(smem_dst);
    asm volatile("cp.async.cg.shared.global [%0], [%1], 16;\n" :: "r"(s), "l"(gsrc));
}
__device__ __forceinline__ uint32_t f2tf32(float x) {
    uint32_t u;
    asm("cvt.rna.tf32.f32 %0, %1;" : "=r"(u) : "f"(x));
    return u;
}
__device__ __forceinline__ float rnd_tf32(float x) {
    return __uint_as_float(f2tf32(x));
}
__device__ __forceinline__ void mma8(float* d, const uint32_t* a, const uint32_t* b) {
    asm volatile(
        "mma.sync.aligned.m16n8k8.row.col.f32.tf32.tf32.f32 "
        "{%0,%1,%2,%3}, {%4,%5,%6,%7}, {%8,%9}, {%0,%1,%2,%3};\n"
        : "+f"(d[0]), "+f"(d[1]), "+f"(d[2]), "+f"(d[3])
        : "r"(a[0]), "r"(a[1]), "r"(a[2]), "r"(a[3]), "r"(b[0]), "r"(b[1]));
}
__device__ __forceinline__ void mma16h(float* d, const uint32_t* a, const uint32_t* b) {
    asm volatile(
        "mma.sync.aligned.m16n8k16.row.col.f32.f16.f16.f32 "
        "{%0,%1,%2,%3}, {%4,%5,%6,%7}, {%8,%9}, {%0,%1,%2,%3};\n"
        : "+f"(d[0]), "+f"(d[1]), "+f"(d[2]), "+f"(d[3])
        : "r"(a[0]), "r"(a[1]), "r"(a[2]), "r"(a[3]), "r"(b[0]), "r"(b[1]));
}
__device__ __forceinline__ void ldmx4(uint32_t* r, uint32_t addr) {
    asm volatile("ldmatrix.sync.aligned.m8n8.x4.shared.b16 {%0,%1,%2,%3}, [%4];"
                 : "=r"(r[0]), "=r"(r[1]), "=r"(r[2]), "=r"(r[3]) : "r"(addr));
}
__device__ __forceinline__ void ldmx2(uint32_t* r, uint32_t addr) {
    asm volatile("ldmatrix.sync.aligned.m8n8.x2.shared.b16 {%0,%1}, [%2];"
                 : "=r"(r[0]), "=r"(r[1]) : "r"(addr));
}
__device__ __forceinline__ uint32_t smem_u32(const void* p) {
    return (uint32_t)__cvta_generic_to_shared(p);
}

// ---------------- elementwise kernels ---------------------------------------
struct WSet {
    const float4* src[7];
    __half* dst[7];
    int n4[7];
};

// streaming fp32 -> fp16 weight convert: 32B load / 16B store per iter
__global__ void round_weights_kernel(WSet ws) {
    int reg = blockIdx.y;
    const float4* src = ws.src[reg];
    uint4* dst = (uint4*)ws.dst[reg];
    int n8 = ws.n4[reg] >> 1;    // 8-float chunks
    int stride = gridDim.x * blockDim.x;
    for (int i = blockIdx.x * blockDim.x + threadIdx.x; i < n8; i += stride) {
        float4 v0 = __ldcs(src + 2 * i);
        float4 v1 = __ldcs(src + 2 * i + 1);
        __half2 h0 = __floats2half2_rn(v0.x, v0.y);
        __half2 h1 = __floats2half2_rn(v0.z, v0.w);
        __half2 h2 = __floats2half2_rn(v1.x, v1.y);
        __half2 h3 = __floats2half2_rn(v1.z, v1.w);
        uint4 o;
        o.x = *(uint32_t*)&h0; o.y = *(uint32_t*)&h1;
        o.z = *(uint32_t*)&h2; o.w = *(uint32_t*)&h3;
        __stcs(dst + i, o);
    }
}

// RMSNorm: fp32 in, fp16 out (feeds GEMM A side)
__global__ void rmsnorm_kernel(const float* __restrict__ x,
                               const float* __restrict__ w,
                               __half* __restrict__ out) {
    int row = blockIdx.x;
    int tid = threadIdx.x;
    const float4 xv = ((const float4*)(x + (size_t)row * DD))[tid];
    float ss = xv.x*xv.x + xv.y*xv.y + xv.z*xv.z + xv.w*xv.w;
    #pragma unroll
    for (int o = 16; o; o >>= 1) ss += __shfl_xor_sync(0xffffffffu, ss, o);
    __shared__ float red[8];
    if ((tid & 31) == 0) red[tid >> 5] = ss;
    __syncthreads();
    if (tid < 32) {
        float v = (tid < 8) ? red[tid] : 0.f;
        #pragma unroll
        for (int o = 4; o; o >>= 1) v += __shfl_xor_sync(0xffffffffu, v, o);
        if (tid == 0) red[0] = v;
    }
    __syncthreads();
    float inv = rsqrtf(red[0] * (1.0f / DD) + 1e-6f);
    float4 wv = ((const float4*)w)[tid];
    __half2 h01 = __floats2half2_rn(xv.x * inv * wv.x, xv.y * inv * wv.y);
    __half2 h23 = __floats2half2_rn(xv.z * inv * wv.z, xv.w * inv * wv.w);
    uint2 o;
    o.x = *(uint32_t*)&h01;
    o.y = *(uint32_t*)&h23;
    ((uint2*)(out + (size_t)row * DD))[tid] = o;
}

// RoPE: reads fp32 q/k, writes rotated values as fp16 hi/lo pairs
__global__ void rope_kernel(const float* __restrict__ q, const float* __restrict__ k,
                            __half* __restrict__ qhi, __half* __restrict__ qlo,
                            __half* __restrict__ khi, __half* __restrict__ klo) {
    int t = blockIdx.x * blockDim.x + threadIdx.x;
    int total = MR * 512;
    const float* p = (t < total) ? q : k;
    __half* ohi = (t < total) ? qhi : khi;
    __half* olo = (t < total) ? qlo : klo;
    int u = (t < total) ? t : (t - total);
    int m  = u >> 9;
    int pr = u & 511;
    int hh = pr >> 5;
    int i  = pr & 31;
    int s  = m & (SS - 1);
    float inv = expf(-(float)i * 0.28782313662425576f);   // ln(10000)/32
    float ang = (float)s * inv;
    float c = cosf(ang), sn = sinf(ang);
    size_t base = (size_t)m * DD + hh * HDIM + i;
    float x1 = p[base];
    float x2 = p[base + 32];
    float y1 = x1 * c - x2 * sn;
    float y2 = x2 * c + x1 * sn;
    __half h1 = __float2half_rn(y1);
    __half h2 = __float2half_rn(y2);
    __half l1 = __float2half_rn(y1 - __half2float(h1));
    __half l2 = __float2half_rn(y2 - __half2float(h2));
    ohi[base] = h1; ohi[base + 32] = h2;
    olo[base] = l1; olo[base + 32] = l2;
}

// silu(gate) * up -> fp16 act
__global__ void silu_mul_kernel(const float* __restrict__ g,
                                const float* __restrict__ u,
                                __half* __restrict__ act) {
    int i = blockIdx.x * blockDim.x + threadIdx.x;
    float4 gv = ((const float4*)g)[i];
    float4 uv = ((const float4*)u)[i];
    float a0 = uv.x * gv.x / (1.f + expf(-gv.x));
    float a1 = uv.y * gv.y / (1.f + expf(-gv.y));
    float a2 = uv.z * gv.z / (1.f + expf(-gv.z));
    float a3 = uv.w * gv.w / (1.f + expf(-gv.w));
    __half2 h01 = __floats2half2_rn(a0, a1);
    __half2 h23 = __floats2half2_rn(a2, a3);
    uint2 o;
    o.x = *(uint32_t*)&h01;
    o.y = *(uint32_t*)&h23;
    ((uint2*)act)[i] = o;
}

// ---------------- fp16 tensor-core GEMM, 3-stage cp.async ------------------
// C[M,N](fp32) = A[M,K](fp16) @ W[N,K](fp16)^T (+bias, +res, opt tf32-round).
// 128x128x32 tile, 256 threads, 8 warps (2x4), warp tile 64x32.

struct GemmArgs {
    const __half* w[3];
    const float* b[3];
    float* c[3];
    int rnd[3];          // round output to tf32 (for V, feeds phase-D mma)
};

#define HS_STR 40                         // halfs per smem row (80 B, pad 8)
#define HS_TILE (128 * HS_STR)            // halfs per stage per matrix
#define GEMM_SMEM (6 * HS_TILE * 2)       // 3 stages x (A+B) bytes = 61440

template<bool HAS_BIAS, bool HAS_RES>
__global__ void __launch_bounds__(256)
gemm_f16(const __half* __restrict__ A, GemmArgs args,
         const float* __restrict__ res, int M, int N, int K) {
    const __half* __restrict__ W = args.w[blockIdx.z];
    const float* __restrict__ bias = args.b[blockIdx.z];
    float* __restrict__ C = args.c[blockIdx.z];
    const bool do_rnd = args.rnd[blockIdx.z] != 0;

    extern __shared__ __half smh[];
    __half* Asb = smh;                    // 3 stages of [128][40]
    __half* Bsb = smh + 3 * HS_TILE;

    int bm = blockIdx.y, bn = blockIdx.x;
    int tid = threadIdx.x;
    int lane = tid & 31, warp = tid >> 5;
    int wm = (warp >> 2) * 64;
    int wn = (warp & 3) * 32;
    int r = lane >> 2, cq = lane & 3;

    float acc[4][4][4];
    #pragma unroll
    for (int i = 0; i < 4; i++)
        #pragma unroll
        for (int j = 0; j < 4; j++)
            #pragma unroll
            for (int t = 0; t < 4; t++) acc[i][j][t] = 0.f;

    const __half* Abase = A + (size_t)(bm * 128) * K;
    const __half* Wbase = W + (size_t)(bn * 128) * K;
    int lr = tid >> 2;
    int lc = (tid & 3) * 8;

    auto load_tile = [&](int st, int k0) {
        __half* As = Asb + st * HS_TILE;
        __half* Bs = Bsb + st * HS_TILE;
        #pragma unroll
        for (int i = 0; i < 2; i++) {
            int row = lr + 64 * i;
            cp16(&As[row * HS_STR + lc], Abase + (size_t)row * K + k0 + lc);
            cp16(&Bs[row * HS_STR + lc], Wbase + (size_t)row * K + k0 + lc);
        }
    };

    int nk = K >> 5;
    load_tile(0, 0);
    asm volatile("cp.async.commit_group;\n" ::);
    load_tile(1, 32);
    asm volatile("cp.async.commit_group;\n" ::);

    int a_row = lane & 15, a_col = (lane >> 4) * 8;
    int b_row = lane & 7,  b_col = ((lane >> 3) & 1) * 8;

    int s = 0;
    for (int kt = 0; kt < nk; kt++) {
        if (kt + 1 < nk) {
            asm volatile("cp.async.wait_group 1;\n" ::);
        } else {
            asm volatile("cp.async.wait_group 0;\n" ::);
        }
        __syncthreads();
        if (kt + 2 < nk) {
            int s2 = s + 2; if (s2 >= 3) s2 -= 3;
            load_tile(s2, (kt + 2) * 32);
            asm volatile("cp.async.commit_group;\n" ::);
        }

        const __half* As = Asb + s * HS_TILE;
        const __half* Bs = Bsb + s * HS_TILE;
        #pragma unroll
        for (int ks = 0; ks < 2; ks++) {
            int kb = ks * 16;
            uint32_t af[4][4], bf[4][2];
            #pragma unroll
            for (int mt = 0; mt < 4; mt++)
                ldmx4(af[mt], smem_u32(&As[(wm + mt * 16 + a_row) * HS_STR + kb + a_col]));
            #pragma unroll
            for (int nt = 0; nt < 4; nt++)
                ldmx2(bf[nt], smem_u32(&Bs[(wn + nt * 8 + b_row) * HS_STR + kb + b_col]));
            #pragma unroll
            for (int mt = 0; mt < 4; mt++)
                #pragma unroll
                for (int nt = 0; nt < 4; nt++)
                    mma16h(acc[mt][nt], af[mt], bf[nt]);
        }
        s = s + 1; if (s >= 3) s -= 3;
    }

    // epilogue (fp32 out)
    #pragma unroll
    for (int mt = 0; mt < 4; mt++) {
        int row0 = bm * 128 + wm + mt * 16 + r;
        #pragma unroll
        for (int nt = 0; nt < 4; nt++) {
            int col = bn * 128 + wn + nt * 8 + 2 * cq;
            float2 v0 = make_float2(acc[mt][nt][0], acc[mt][nt][1]);
            float2 v1 = make_float2(acc[mt][nt][2], acc[mt][nt][3]);
            if (HAS_BIAS) {
                float2 bb = *(const float2*)(bias + col);
                v0.x += bb.x; v0.y += bb.y; v1.x += bb.x; v1.y += bb.y;
            }
            size_t i0 = (size_t)row0 * N + col;
            size_t i1 = i0 + (size_t)8 * N;
            if (HAS_RES) {
                float2 r0 = *(const float2*)(res + i0);
                float2 r1 = *(const float2*)(res + i1);
                v0.x += r0.x; v0.y += r0.y; v1.x += r1.x; v1.y += r1.y;
            }
            if (do_rnd) {
                v0.x = rnd_tf32(v0.x); v0.y = rnd_tf32(v0.y);
                v1.x = rnd_tf32(v1.x); v1.y = rnd_tf32(v1.y);
            }
            *(float2*)(C + i0) = v0;
            *(float2*)(C + i1) = v1;
        }
    }
}

// ---------------- sliding-window attention (512 threads) -------------------
#define KQ_STR 72                        // halfs per q/k smem row (144 B)
#define AQ_STR 68                        // floats per V smem row
#define ASC_STR 321
#define OFF_QHI 0
#define OFF_QLO 9216
#define OFF_KV  18432
#define OFF_SC  55296
#define ATTN_SMEM (55296 + 64 * ASC_STR * 4)   // 137472

__global__ void __launch_bounds__(512)
attn_kernel(const __half* __restrict__ qhi_g, const __half* __restrict__ qlo_g,
            const __half* __restrict__ khi_g, const __half* __restrict__ klo_g,
            const float* __restrict__ v, __half* __restrict__ ao,
            float* __restrict__ attn_out) {
    extern __shared__ char smraw[];
    __half* Qhi = (__half*)(smraw + OFF_QHI);
    __half* Qlo = (__half*)(smraw + OFF_QLO);
    __half* Khi[2] = { (__half*)(smraw + OFF_KV),         (__half*)(smraw + OFF_KV + 18432) };
    __half* Klo[2] = { (__half*)(smraw + OFF_KV + 9216),  (__half*)(smraw + OFF_KV + 27648) };
    float*  Vb[2]  = { (float*)(smraw + OFF_KV),          (float*)(smraw + OFF_KV + 17408) };
    float* sc = (float*)(smraw + OFF_SC);

    int q0 = blockIdx.x * 64;
    int bh = blockIdx.y;
    int b  = bh >> 4, h = bh & 15;
    int tid = threadIdx.x;
    int lane = tid & 31, warp = tid >> 5;
    int wq = (warp & 3) * 16;
    int wn = (warp >> 2) * 16;
    int r = lane >> 2, cq = lane & 3;
    int a_row = lane & 15, a_col = (lane >> 4) * 8;
    int b_row = lane & 7,  b_col = ((lane >> 3) & 1) * 8;
    const float scale = 0.125f;

    const __half* khb = khi_g + (size_t)(b * SS) * DD + h * HDIM;
    const __half* klb = klo_g + (size_t)(b * SS) * DD + h * HDIM;
    const float*  vbase = v + (size_t)(b * SS) * DD + h * HDIM;

    {
        int qq = tid >> 3, dq = (tid & 7) * 8;
        const __half* qh = qhi_g + (size_t)(b * SS + q0 + qq) * DD + h * HDIM + dq;
        const __half* ql = qlo_g + (size_t)(b * SS + q0 + qq) * DD + h * HDIM + dq;
        cp16(&Qhi[qq * KQ_STR + dq], qh);
        cp16(&Qlo[qq * KQ_STR + dq], ql);
    }

    auto loadK = [&](int buf, int jb) {
        int kk = tid >> 3, dq = (tid & 7) * 8;
        int j = jb + kk;
        if (j >= 0) {
            cp16(&Khi[buf][kk * KQ_STR + dq], khb + (size_t)j * DD + dq);
            cp16(&Klo[buf][kk * KQ_STR + dq], klb + (size_t)j * DD + dq);
        } else {
            uint4 z = make_uint4(0, 0, 0, 0);
            *(uint4*)&Khi[buf][kk * KQ_STR + dq] = z;
            *(uint4*)&Klo[buf][kk * KQ_STR + dq] = z;
        }
    };

    // -------- Phase A: scores via fp16 hi/lo 3-product mma ----------------
    loadK(0, q0 - 256);
    asm volatile("cp.async.commit_group;\n" ::);
    for (int c = 0; c < 5; c++) {
        if (c < 4) {
            loadK((c + 1) & 1, q0 - 256 + (c + 1) * 64);
            asm volatile("cp.async.commit_group;\n" ::);
            asm volatile("cp.async.wait_group 1;\n" ::);
        } else {
            asm volatile("cp.async.wait_group 0;\n" ::);
        }
        __syncthreads();
        const __half* KH = Khi[c & 1];
        const __half* KL = Klo[c & 1];

        float acc[2][4];
        #pragma unroll
        for (int i = 0; i < 2; i++)
            #pragma unroll
            for (int j = 0; j < 4; j++) acc[i][j] = 0.f;

        #pragma unroll
        for (int ks = 0; ks < 4; ks++) {
            int kb = ks * 16;
            uint32_t ahi[4], alo[4];
            ldmx4(ahi, smem_u32(&Qhi[(wq + a_row) * KQ_STR + kb + a_col]));
            ldmx4(alo, smem_u32(&Qlo[(wq + a_row) * KQ_STR + kb + a_col]));
            #pragma unroll
            for (int nt = 0; nt < 2; nt++) {
                uint32_t bhi[2], blo[2];
                ldmx2(bhi, smem_u32(&KH[(wn + nt * 8 + b_row) * KQ_STR + kb + b_col]));
                ldmx2(blo, smem_u32(&KL[(wn + nt * 8 + b_row) * KQ_STR + kb + b_col]));
                mma16h(acc[nt], ahi, bhi);
                mma16h(acc[nt], ahi, blo);
                mma16h(acc[nt], alo, bhi);
            }
        }

        int jb = q0 - 256 + c * 64;
        #pragma unroll
        for (int nt = 0; nt < 2; nt++) {
            int jl = wn + nt * 8 + 2 * cq;
            #pragma unroll
            for (int u = 0; u < 2; u++) {
                int qq = wq + r + u * 8;
                int qi = q0 + qq;
                #pragma unroll
                for (int w2 = 0; w2 < 2; w2++) {
                    int jj = jb + jl + w2;
                    bool valid = (jj >= 0) && (jj <= qi) && (qi - jj < WIN);
                    sc[qq * ASC_STR + c * 64 + jl + w2] =
                        valid ? acc[nt][u * 2 + w2] * scale : -1e30f;
                }
            }
        }
        __syncthreads();
    }

    // -------- Phase B: softmax, 8 threads per row -------------------------
    {
        int qq = tid >> 3, g = tid & 7;
        float* row = sc + qq * ASC_STR;
        float mx = -1e30f;
        for (int s = g; s < 320; s += 8) mx = fmaxf(mx, row[s]);
        mx = fmaxf(mx, __shfl_xor_sync(0xffffffffu, mx, 1));
        mx = fmaxf(mx, __shfl_xor_sync(0xffffffffu, mx, 2));
        mx = fmaxf(mx, __shfl_xor_sync(0xffffffffu, mx, 4));
        float sum = 0.f;
        for (int s = g; s < 320; s += 8) {
            float e = expf(row[s] - mx);
            row[s] = e;
            sum += e;
        }
        sum += __shfl_xor_sync(0xffffffffu, sum, 1);
        sum += __shfl_xor_sync(0xffffffffu, sum, 2);
        sum += __shfl_xor_sync(0xffffffffu, sum, 4);
        float inv = 1.f / sum;
        for (int s = g; s < 320; s += 8) row[s] *= inv;
    }
    __syncthreads();

    // -------- Phase C: write full attn rows (streaming stores) ------------
    {
        int c4 = tid & 255;
        int half = tid >> 8;
        for (int it = 0; it < 32; it++) {
            int qq = it * 2 + half;
            int qi = q0 + qq;
            const float* src = sc + qq * ASC_STR;
            float rr[4];
            #pragma unroll
            for (int u = 0; u < 4; u++) {
                int j = c4 * 4 + u;
                bool in = (j <= qi) && (qi - j < WIN);
                rr[u] = in ? src[j - q0 + 256] : 0.f;
            }
            __stcs(((float4*)(attn_out + ((size_t)bh * SS + qi) * SS)) + c4,
                   make_float4(rr[0], rr[1], rr[2], rr[3]));
        }
    }
    __syncthreads();

    // -------- Phase D: out = P @ V (tf32), double-buffered V ---------------
    float oacc[2][4];
    #pragma unroll
    for (int i = 0; i < 2; i++)
        #pragma unroll
        for (int j = 0; j < 4; j++) oacc[i][j] = 0.f;

    auto loadV = [&](int buf, int jb) {
        #pragma unroll
        for (int i = 0; i < 2; i++) {
            int ch = tid + 512 * i;
            int kk = ch >> 4, dq = (ch & 15) * 4;
            int j = jb + kk;
            if (j >= 0) cp16(&Vb[buf][kk * AQ_STR + dq], vbase + (size_t)j * DD + dq);
            else *(float4*)&Vb[buf][kk * AQ_STR + dq] = make_float4(0.f, 0.f, 0.f, 0.f);
        }
    };

    loadV(0, q0 - 256);
    asm volatile("cp.async.commit_group;\n" ::);
    for (int c = 0; c < 5; c++) {
        if (c < 4) {
            loadV((c + 1) & 1, q0 - 256 + (c + 1) * 64);
            asm volatile("cp.async.commit_group;\n" ::);
            asm volatile("cp.async.wait_group 1;\n" ::);
        } else {
            asm volatile("cp.async.wait_group 0;\n" ::);
        }
        __syncthreads();
        const float* Vs = Vb[c & 1];   // [kk][d]

        #pragma unroll
        for (int kb = 0; kb < 64; kb += 8) {
            uint32_t ah[4];
            ah[0] = f2tf32(sc[(wq + r)     * ASC_STR + c * 64 + kb + cq]);
            ah[1] = f2tf32(sc[(wq + r + 8) * ASC_STR + c * 64 + kb + cq]);
            ah[2] = f2tf32(sc[(wq + r)     * ASC_STR + c * 64 + kb + cq + 4]);
            ah[3] = f2tf32(sc[(wq + r + 8) * ASC_STR + c * 64 + kb + cq + 4]);
            #pragma unroll
            for (int nt = 0; nt < 2; nt++) {
                uint32_t bb[2];
                bb[0] = __float_as_uint(Vs[(kb + cq)     * AQ_STR + wn + nt * 8 + r]);
                bb[1] = __float_as_uint(Vs[(kb + cq + 4) * AQ_STR + wn + nt * 8 + r]);
                mma8(oacc[nt], ah, bb);
            }
        }
        __syncthreads();
    }

    #pragma unroll
    for (int nt = 0; nt < 2; nt++) {
        int d0 = wn + nt * 8 + 2 * cq;
        size_t b0 = ((size_t)(b * SS + q0 + wq + r))     * DD + h * HDIM + d0;
        size_t b1 = ((size_t)(b * SS + q0 + wq + r + 8)) * DD + h * HDIM + d0;
        __half2 h0 = __floats2half2_rn(oacc[nt][0], oacc[nt][1]);
        __half2 h1 = __floats2half2_rn(oacc[nt][2], oacc[nt][3]);
        *(__half2*)(ao + b0) = h0;
        *(__half2*)(ao + b1) = h1;
    }
}

// ---------------- launcher -------------------------------------------------
extern "C" void kernel_launch(void* const* d_in, const int* in_sizes, int n_in,
                              void* d_out, int out_size) {
    const float* x   = (const float*)d_in[0];
    const float* wq  = (const float*)d_in[1];
    const float* bq  = (const float*)d_in[2];
    const float* wk  = (const float*)d_in[3];
    const float* bk  = (const float*)d_in[4];
    const float* wv  = (const float*)d_in[5];
    const float* bv  = (const float*)d_in[6];
    const float* wo  = (const float*)d_in[7];
    const float* bo  = (const float*)d_in[8];
    const float* anw = (const float*)d_in[9];
    const float* fnw = (const float*)d_in[10];
    const float* gw  = (const float*)d_in[11];
    const float* uw  = (const float*)d_in[12];
    const float* dw  = (const float*)d_in[13];

    float* outx = (float*)d_out;                       // [B,S,D]
    float* outa = outx + (size_t)MR * DD;              // [B,H,S,S]

    float *p_q, *p_k, *p_v, *p_x1, *p_gate, *p_up;
    __half *p_hh, *p_h2h, *p_aoh, *p_acth, *p_wh;
    __half *p_qhi, *p_qlo, *p_khi, *p_klo;
    cudaGetSymbolAddress((void**)&p_q,    g_q);
    cudaGetSymbolAddress((void**)&p_k,    g_k);
    cudaGetSymbolAddress((void**)&p_v,    g_v);
    cudaGetSymbolAddress((void**)&p_x1,   g_x1);
    cudaGetSymbolAddress((void**)&p_gate, g_gate);
    cudaGetSymbolAddress((void**)&p_up,   g_up);
    cudaGetSymbolAddress((void**)&p_hh,   g_hh);
    cudaGetSymbolAddress((void**)&p_h2h,  g_h2h);
    cudaGetSymbolAddress((void**)&p_aoh,  g_aoh);
    cudaGetSymbolAddress((void**)&p_acth, g_acth);
    cudaGetSymbolAddress((void**)&p_wh,   g_wh);
    cudaGetSymbolAddress((void**)&p_qhi,  g_qhi);
    cudaGetSymbolAddress((void**)&p_qlo,  g_qlo);
    cudaGetSymbolAddress((void**)&p_khi,  g_khi);
    cudaGetSymbolAddress((void**)&p_klo,  g_klo);

    const size_t MB1 = 1024 * 1024;
    __half* hwq = p_wh;            __half* hwk = p_wh + 1 * MB1;
    __half* hwv = p_wh + 2 * MB1;  __half* hwo = p_wh + 3 * MB1;
    __half* hgw = p_wh + 4 * MB1;  __half* huw = p_wh + 8 * MB1;
    __half* hdw = p_wh + 12 * MB1;

    cudaFuncSetAttribute(attn_kernel,
                         cudaFuncAttributeMaxDynamicSharedMemorySize, ATTN_SMEM);
    cudaFuncSetAttribute(gemm_f16<true, false>,
                         cudaFuncAttributeMaxDynamicSharedMemorySize, GEMM_SMEM);
    cudaFuncSetAttribute(gemm_f16<true, true>,
                         cudaFuncAttributeMaxDynamicSharedMemorySize, GEMM_SMEM);
    cudaFuncSetAttribute(gemm_f16<false, false>,
                         cudaFuncAttributeMaxDynamicSharedMemorySize, GEMM_SMEM);
    cudaFuncSetAttribute(gemm_f16<false, true>,
                         cudaFuncAttributeMaxDynamicSharedMemorySize, GEMM_SMEM);

    // 0) weights -> fp16 in one streaming launch
    {
        WSet ws;
        ws.src[0] = (const float4*)wq; ws.dst[0] = hwq; ws.n4[0] = 262144;
        ws.src[1] = (const float4*)wk; ws.dst[1] = hwk; ws.n4[1] = 262144;
        ws.src[2] = (const float4*)wv; ws.dst[2] = hwv; ws.n4[2] = 262144;
        ws.src[3] = (const float4*)wo; ws.dst[3] = hwo; ws.n4[3] = 262144;
        ws.src[4] = (const float4*)gw; ws.dst[4] = hgw; ws.n4[4] = 1048576;
        ws.src[5] = (const float4*)uw; ws.dst[5] = huw; ws.n4[5] = 1048576;
        ws.src[6] = (const float4*)dw; ws.dst[6] = hdw; ws.n4[6] = 1048576;
        round_weights_kernel<<<dim3(512, 7), 256>>>(ws);
    }

    // 1) attn rmsnorm -> fp16
    rmsnorm_kernel<<<MR, 256>>>(x, anw, p_hh);

    // 2) QKV — one z=3 fp16 launch; V tf32-rounded in epilogue
    {
        GemmArgs a = {};
        a.w[0] = hwq; a.w[1] = hwk; a.w[2] = hwv;
        a.b[0] = bq;  a.b[1] = bk;  a.b[2] = bv;
        a.c[0] = p_q; a.c[1] = p_k; a.c[2] = p_v;
        a.rnd[0] = 0; a.rnd[1] = 0; a.rnd[2] = 1;
        gemm_f16<true, false><<<dim3(DD/128, MR/128, 3), 256, GEMM_SMEM>>>(
            p_hh, a, nullptr, MR, DD, DD);
    }
    // 3) RoPE -> fp16 hi/lo arrays
    rope_kernel<<<(2 * MR * 512) / 256, 256>>>(p_q, p_k, p_qhi, p_qlo, p_khi, p_klo);
    // 4) attention (probs -> outa, context -> g_aoh fp16)
    attn_kernel<<<dim3(SS / 64, BB * HH), 512, ATTN_SMEM>>>(
        p_qhi, p_qlo, p_khi, p_klo, p_v, p_aoh, outa);
    // 5) O proj + bias + residual
    {
        GemmArgs a = {};
        a.w[0] = hwo; a.b[0] = bo; a.c[0] = p_x1;
        gemm_f16<true, true><<<dim3(DD/128, MR/128, 1), 256, GEMM_SMEM>>>(
            p_aoh, a, x, MR, DD, DD);
    }
    // 6) ffn rmsnorm -> fp16
    rmsnorm_kernel<<<MR, 256>>>(p_x1, fnw, p_h2h);
    // 7) gate + up in one z=2 launch
    {
        GemmArgs a = {};
        a.w[0] = hgw; a.w[1] = huw;
        a.c[0] = p_gate; a.c[1] = p_up;
        gemm_f16<false, false><<<dim3(FF/128, MR/128, 2), 256, GEMM_SMEM>>>(
            p_h2h, a, nullptr, MR, FF, DD);
    }
    // 8) act = silu(gate) * up -> fp16
    silu_mul_kernel<<<(MR * FF / 4) / 256, 256>>>(p_gate, p_up, p_acth);
    // 9) down + residual -> final x
    {
        GemmArgs a = {};
        a.w[0] = hdw; a.c[0] = outx;
        gemm_f16<false, true><<<dim3(DD/128, MR/128, 1), 256, GEMM_SMEM>>>(
            p_acth, a, p_x1, MR, DD, FF);
    }
}